// round 5
// baseline (speedup 1.0000x reference)
#include <cuda_runtime.h>
#include <math.h>
#include <stdint.h>

#define B_    2
#define NQ    1024
#define NK    2048
#define DIM_  512
#define HID_  512
#define H_    8
#define HD_   64
#define RBH   64
#define LUT_T 2048

// Static device scratch (no runtime allocation allowed)
__device__ float g_Q[(size_t)B_ * NQ * HID_];
__device__ float g_K[(size_t)B_ * NK * HID_];
__device__ float g_V[(size_t)B_ * NK * HID_];
__device__ float g_attn[(size_t)B_ * NQ * HID_];
__device__ float g_lut[H_ * LUT_T];
__device__ unsigned int g_maxbits[2];
__device__ float g_inv_step2;   // 1 / (d^2 LUT step)

// ---------------------------------------------------------------------------
// TF32 / async helpers
// ---------------------------------------------------------------------------
__device__ __forceinline__ uint32_t f2tf(float x) {
    uint32_t r; asm("cvt.rna.tf32.f32 %0, %1;" : "=r"(r) : "f"(x)); return r;
}
__device__ __forceinline__ void mma8(float* d, const uint32_t* a, uint32_t b0, uint32_t b1) {
    asm volatile(
        "mma.sync.aligned.m16n8k8.row.col.f32.tf32.tf32.f32 "
        "{%0,%1,%2,%3}, {%4,%5,%6,%7}, {%8,%9}, {%0,%1,%2,%3};"
        : "+f"(d[0]), "+f"(d[1]), "+f"(d[2]), "+f"(d[3])
        : "r"(a[0]), "r"(a[1]), "r"(a[2]), "r"(a[3]), "r"(b0), "r"(b1));
}
__device__ __forceinline__ void cpa16(uint32_t s, const float* g) {
    asm volatile("cp.async.cg.shared.global [%0], [%1], 16;" :: "r"(s), "l"(g));
}

// ---------------------------------------------------------------------------
// LUT pipeline (bias as function of squared distance)
// ---------------------------------------------------------------------------
__global__ void init_kernel() {
    if (threadIdx.x < 2) g_maxbits[threadIdx.x] = 0u;
}

__global__ __launch_bounds__(256) void norm_kernel(
    const float* __restrict__ qc, const float* __restrict__ kc)
{
    const int NQT = B_ * NQ;
    const int NKT = B_ * NK;
    int i = blockIdx.x * 256 + threadIdx.x;
    float n = 0.f;
    int which = 0;
    if (i < NQT) {
        float x = qc[i*3], y = qc[i*3+1], z = qc[i*3+2];
        n = sqrtf(fmaf(x,x,fmaf(y,y,z*z)));
    } else if (i < NQT + NKT) {
        int j = i - NQT;
        float x = kc[j*3], y = kc[j*3+1], z = kc[j*3+2];
        n = sqrtf(fmaf(x,x,fmaf(y,y,z*z)));
        which = 1;
    }
    atomicMax(&g_maxbits[which], __float_as_uint(n));
}

__global__ __launch_bounds__(256) void lut_kernel(
    const float* __restrict__ W1, const float* __restrict__ b1,
    const float* __restrict__ W2, const float* __restrict__ b2)
{
    __shared__ float sW1[RBH], sb1[RBH], sW2[RBH * H_];
    int t = threadIdx.x;
    if (t < RBH) { sW1[t] = W1[t]; sb1[t] = b1[t]; }
    for (int i = t; i < RBH * H_; i += 256) sW2[i] = W2[i];
    __syncthreads();

    float dmax = __uint_as_float(g_maxbits[0]) + __uint_as_float(g_maxbits[1]) + 1e-3f;
    float step2 = dmax * dmax / (float)(LUT_T - 1);
    if (blockIdx.x == 0 && t == 0) g_inv_step2 = 1.0f / step2;

    int i = blockIdx.x * 256 + t;
    if (i >= LUT_T) return;
    float d = sqrtf(step2 * (float)i);

    float o[H_];
    #pragma unroll
    for (int hh = 0; hh < H_; hh++) o[hh] = b2[hh];
    #pragma unroll 8
    for (int j = 0; j < RBH; j++) {
        float x = fmaf(d, sW1[j], sb1[j]);
        float s = __fdividef(x, 1.0f + __expf(-x));
        #pragma unroll
        for (int hh = 0; hh < H_; hh++)
            o[hh] = fmaf(s, sW2[j * H_ + hh], o[hh]);
    }
    #pragma unroll
    for (int hh = 0; hh < H_; hh++) g_lut[hh * LUT_T + i] = o[hh];
}

// ---------------------------------------------------------------------------
// TF32 tensor-core GEMM body: C[*,N] = A[*,K] @ B[K,N] for a 128x64 tile at
// (row0, blockIdx.x*64). 256 thr, 8 warps (4m x 2n), double-buffered.
// ---------------------------------------------------------------------------
#define AS_STR 20
#define BS_STR 72

__device__ __forceinline__ void gemm_tf32_body(
    const float* __restrict__ A, const float* __restrict__ Bm,
    float* __restrict__ C, int N, int K, int row0,
    uint32_t* As, uint32_t* Bs)
{
    const int tid  = threadIdx.x;
    const int lane = tid & 31;
    const int wid  = tid >> 5;
    const int wm   = (wid >> 1) * 32;
    const int wn   = (wid & 1) * 32;
    const int col0 = blockIdx.x * 64;
    const int lq   = lane >> 2;
    const int lr   = lane & 3;

    const int ar = tid >> 1, ac = (tid & 1) * 8;
    const int bk = tid >> 4, bn = (tid & 15) * 4;

    float acc[2][4][4] = {};

    {
        float4 a0 = *(const float4*)&A[(size_t)(row0 + ar) * K + ac];
        float4 a1 = *(const float4*)&A[(size_t)(row0 + ar) * K + ac + 4];
        float4 b0 = *(const float4*)&Bm[(size_t)bk * N + col0 + bn];
        *(uint4*)&As[ar * AS_STR + ac]     = make_uint4(f2tf(a0.x), f2tf(a0.y), f2tf(a0.z), f2tf(a0.w));
        *(uint4*)&As[ar * AS_STR + ac + 4] = make_uint4(f2tf(a1.x), f2tf(a1.y), f2tf(a1.z), f2tf(a1.w));
        *(uint4*)&Bs[bk * BS_STR + bn]     = make_uint4(f2tf(b0.x), f2tf(b0.y), f2tf(b0.z), f2tf(b0.w));
    }
    __syncthreads();

    int buf = 0;
    for (int k0 = 0; k0 < K; k0 += 16) {
        const bool more = (k0 + 16) < K;
        float4 na0, na1, nb0;
        if (more) {
            na0 = *(const float4*)&A[(size_t)(row0 + ar) * K + k0 + 16 + ac];
            na1 = *(const float4*)&A[(size_t)(row0 + ar) * K + k0 + 16 + ac + 4];
            nb0 = *(const float4*)&Bm[(size_t)(k0 + 16 + bk) * N + col0 + bn];
        }
        const uint32_t* Ab = As + buf * (128 * AS_STR);
        const uint32_t* Bb = Bs + buf * (16 * BS_STR);

        #pragma unroll
        for (int s = 0; s < 2; s++) {
            uint32_t af[2][4], bf[4][2];
            const int kc_ = s * 8 + lr;
            #pragma unroll
            for (int mf = 0; mf < 2; mf++) {
                const int r = wm + mf * 16 + lq;
                af[mf][0] = Ab[r * AS_STR + kc_];
                af[mf][1] = Ab[(r + 8) * AS_STR + kc_];
                af[mf][2] = Ab[r * AS_STR + kc_ + 4];
                af[mf][3] = Ab[(r + 8) * AS_STR + kc_ + 4];
            }
            #pragma unroll
            for (int nf = 0; nf < 4; nf++) {
                const int cc = wn + nf * 8 + lq;
                bf[nf][0] = Bb[kc_ * BS_STR + cc];
                bf[nf][1] = Bb[(kc_ + 4) * BS_STR + cc];
            }
            #pragma unroll
            for (int mf = 0; mf < 2; mf++)
                #pragma unroll
                for (int nf = 0; nf < 4; nf++)
                    mma8(acc[mf][nf], af[mf], bf[nf][0], bf[nf][1]);
        }

        if (more) {
            buf ^= 1;
            uint32_t* Aw = As + buf * (128 * AS_STR);
            uint32_t* Bw = Bs + buf * (16 * BS_STR);
            *(uint4*)&Aw[ar * AS_STR + ac]     = make_uint4(f2tf(na0.x), f2tf(na0.y), f2tf(na0.z), f2tf(na0.w));
            *(uint4*)&Aw[ar * AS_STR + ac + 4] = make_uint4(f2tf(na1.x), f2tf(na1.y), f2tf(na1.z), f2tf(na1.w));
            *(uint4*)&Bw[bk * BS_STR + bn]     = make_uint4(f2tf(nb0.x), f2tf(nb0.y), f2tf(nb0.z), f2tf(nb0.w));
            __syncthreads();
        }
    }

    #pragma unroll
    for (int mf = 0; mf < 2; mf++)
        #pragma unroll
        for (int nf = 0; nf < 4; nf++) {
            const int r = row0 + wm + mf * 16 + lq;
            const int c = col0 + wn + nf * 8 + 2 * lr;
            *(float2*)&C[(size_t)r * N + c]       = make_float2(acc[mf][nf][0], acc[mf][nf][1]);
            *(float2*)&C[(size_t)(r + 8) * N + c] = make_float2(acc[mf][nf][2], acc[mf][nf][3]);
        }
}

__global__ __launch_bounds__(256) void gemm_kernel(
    const float* __restrict__ A, const float* __restrict__ Bm,
    float* __restrict__ C, int N, int K)
{
    __shared__ uint32_t As[2 * 128 * AS_STR];
    __shared__ uint32_t Bs[2 * 16 * BS_STR];
    gemm_tf32_body(A, Bm, C, N, K, blockIdx.y * 128, As, Bs);
}

// Q, K, V projections fused: blockIdx.y in [0,80): [0,16)->Q, [16,48)->K, [48,80)->V
__global__ __launch_bounds__(256) void gemm_qkv_kernel(
    const float* __restrict__ q_in, const float* __restrict__ kv_in,
    const float* __restrict__ Wq, const float* __restrict__ Wk,
    const float* __restrict__ Wv,
    float* __restrict__ Qo, float* __restrict__ Ko, float* __restrict__ Vo)
{
    __shared__ uint32_t As[2 * 128 * AS_STR];
    __shared__ uint32_t Bs[2 * 16 * BS_STR];
    int by = blockIdx.y;
    const float *A, *Bw; float* C;
    if (by < 16)      { A = q_in;  Bw = Wq; C = Qo; }
    else if (by < 48) { A = kv_in; Bw = Wk; C = Ko; by -= 16; }
    else              { A = kv_in; Bw = Wv; C = Vo; by -= 48; }
    gemm_tf32_body(A, Bw, C, HID_, DIM_, by * 128, As, Bs);
}

// ---------------------------------------------------------------------------
// TF32 flash attention, warp-level split-K.
// CTA = 64 q rows, 8 warps = 4 row-groups x 2 k-split warps.
// K/V double-buffered via cp.async (raw fp32, cvt at fragment load).
// ---------------------------------------------------------------------------
#define KV_STR 76
#define P_STR  68
// float offsets into dynamic smem
#define OFF_K   0                       // 2 * 64 * 76 = 9728
#define OFF_V   9728                    // 9728
#define OFF_P   19456                   // 64 * 68 = 4352
#define OFF_LUT 23808                   // 2048
#define OFF_KC  25856                   // 2 * 192 = 384
#define ATT_SMEM_FLOATS 26240           // * 4 = 104960 B

__global__ __launch_bounds__(256, 2) void attn_kernel(
    const float* __restrict__ qc, const float* __restrict__ kc)
{
    extern __shared__ float sm[];
    float*    slut = sm + OFF_LUT;
    uint32_t* Pu   = (uint32_t*)(sm + OFF_P);

    const int b   = blockIdx.z;
    const int h   = blockIdx.y;
    const int q0  = blockIdx.x * 64;
    const int tid = threadIdx.x;
    const int lane = tid & 31;
    const int w    = tid >> 5;
    const int rowgrp = w >> 1;
    const int ksplit = w & 1;
    const int lq   = lane >> 2;
    const int lr   = lane & 3;

    uint32_t sb;
    asm("{.reg .u64 t; cvta.to.shared.u64 t, %1; cvt.u32.u64 %0, t;}" : "=r"(sb) : "l"(sm));

    // stage LUT
    for (int i = tid; i < LUT_T; i += 256) slut[i] = g_lut[h * LUT_T + i];
    const float inv_step2 = g_inv_step2;

    // Q fragments in registers (scale folded)
    uint32_t qa[8][4];
    {
        const size_t r0 = ((size_t)(b * NQ + q0 + rowgrp * 16 + lq)) * HID_ + h * HD_;
        const size_t r1 = r0 + 8 * HID_;
        #pragma unroll
        for (int ks = 0; ks < 8; ks++) {
            qa[ks][0] = f2tf(0.125f * g_Q[r0 + ks * 8 + lr]);
            qa[ks][1] = f2tf(0.125f * g_Q[r1 + ks * 8 + lr]);
            qa[ks][2] = f2tf(0.125f * g_Q[r0 + ks * 8 + lr + 4]);
            qa[ks][3] = f2tf(0.125f * g_Q[r1 + ks * 8 + lr + 4]);
        }
    }
    float q0x, q0y, q0z, q1x, q1y, q1z;
    {
        const float* p0 = qc + ((size_t)b * NQ + q0 + rowgrp * 16 + lq) * 3;
        const float* p1 = p0 + 8 * 3;
        q0x = p0[0]; q0y = p0[1]; q0z = p0[2];
        q1x = p1[0]; q1y = p1[1]; q1z = p1[2];
    }

    float of[8][4] = {};
    float m0 = -INFINITY, m1 = -INFINITY, l0 = 0.f, l1 = 0.f;

    const float* Kp  = g_K + ((size_t)b * NK) * HID_ + h * HD_;
    const float* Vp  = g_V + ((size_t)b * NK) * HID_ + h * HD_;
    const float* kcb = kc + (size_t)b * NK * 3;

    const int lkey = tid >> 2;
    const int ldb  = (tid & 3) * 16;

    // async tile loader
    auto issue = [&](int t, int bf) {
        const float* kg = Kp + (size_t)(t * 64 + lkey) * HID_ + ldb;
        const float* vg = Vp + (size_t)(t * 64 + lkey) * HID_ + ldb;
        uint32_t kd = sb + (OFF_K + bf * 4864 + lkey * KV_STR + ldb) * 4;
        uint32_t vd = sb + (OFF_V + bf * 4864 + lkey * KV_STR + ldb) * 4;
        #pragma unroll
        for (int u = 0; u < 4; u++) {
            cpa16(kd + u * 16, kg + u * 4);
            cpa16(vd + u * 16, vg + u * 4);
        }
        if (tid < 48)
            cpa16(sb + (OFF_KC + bf * 192 + tid * 4) * 4, kcb + (size_t)t * 192 + tid * 4);
        asm volatile("cp.async.commit_group;" ::: "memory");
    };

    issue(0, 0);
    int buf = 0;
    const int NT = NK / 64;

    for (int t = 0; t < NT; t++) {
        if (t + 1 < NT) {
            issue(t + 1, buf ^ 1);
            asm volatile("cp.async.wait_group 1;" ::: "memory");
        } else {
            asm volatile("cp.async.wait_group 0;" ::: "memory");
        }
        __syncthreads();

        const float* Kb  = sm + OFF_K + buf * 4864;
        const float* Vb  = sm + OFF_V + buf * 4864;
        const float* kcs = sm + OFF_KC + buf * 192;

        // ---- QK^T over this warp's 32-key slice ----
        float sacc[4][4] = {};
        #pragma unroll
        for (int ks = 0; ks < 8; ks++) {
            const int dcol = ks * 8 + lr;
            #pragma unroll
            for (int nf = 0; nf < 4; nf++) {
                const int key = ksplit * 32 + nf * 8 + lq;
                uint32_t b0 = f2tf(Kb[key * KV_STR + dcol]);
                uint32_t b1 = f2tf(Kb[key * KV_STR + dcol + 4]);
                mma8(sacc[nf], qa[ks], b0, b1);
            }
        }

        // ---- bias + online softmax (warp-private over its slice) ----
        float rm0 = -INFINITY, rm1 = -INFINITY;
        #pragma unroll
        for (int nf = 0; nf < 4; nf++) {
            const int c0 = ksplit * 32 + nf * 8 + 2 * lr;
            float kx0 = kcs[c0*3+0], ky0 = kcs[c0*3+1], kz0 = kcs[c0*3+2];
            float kx1 = kcs[c0*3+3], ky1 = kcs[c0*3+4], kz1 = kcs[c0*3+5];
            {
                float dx = q0x-kx0, dy = q0y-ky0, dz = q0z-kz0;
                float u = fmaf(dx,dx,fmaf(dy,dy,dz*dz)) * inv_step2;
                int ii = (int)u; ii = (ii > LUT_T-2) ? LUT_T-2 : ii;
                float fr = u - (float)ii;
                sacc[nf][0] += fmaf(fr, slut[ii+1]-slut[ii], slut[ii]);
            }
            {
                float dx = q0x-kx1, dy = q0y-ky1, dz = q0z-kz1;
                float u = fmaf(dx,dx,fmaf(dy,dy,dz*dz)) * inv_step2;
                int ii = (int)u; ii = (ii > LUT_T-2) ? LUT_T-2 : ii;
                float fr = u - (float)ii;
                sacc[nf][1] += fmaf(fr, slut[ii+1]-slut[ii], slut[ii]);
            }
            {
                float dx = q1x-kx0, dy = q1y-ky0, dz = q1z-kz0;
                float u = fmaf(dx,dx,fmaf(dy,dy,dz*dz)) * inv_step2;
                int ii = (int)u; ii = (ii > LUT_T-2) ? LUT_T-2 : ii;
                float fr = u - (float)ii;
                sacc[nf][2] += fmaf(fr, slut[ii+1]-slut[ii], slut[ii]);
            }
            {
                float dx = q1x-kx1, dy = q1y-ky1, dz = q1z-kz1;
                float u = fmaf(dx,dx,fmaf(dy,dy,dz*dz)) * inv_step2;
                int ii = (int)u; ii = (ii > LUT_T-2) ? LUT_T-2 : ii;
                float fr = u - (float)ii;
                sacc[nf][3] += fmaf(fr, slut[ii+1]-slut[ii], slut[ii]);
            }
            rm0 = fmaxf(rm0, fmaxf(sacc[nf][0], sacc[nf][1]));
            rm1 = fmaxf(rm1, fmaxf(sacc[nf][2], sacc[nf][3]));
        }
        rm0 = fmaxf(rm0, __shfl_xor_sync(0xffffffffu, rm0, 1));
        rm0 = fmaxf(rm0, __shfl_xor_sync(0xffffffffu, rm0, 2));
        rm1 = fmaxf(rm1, __shfl_xor_sync(0xffffffffu, rm1, 1));
        rm1 = fmaxf(rm1, __shfl_xor_sync(0xffffffffu, rm1, 2));

        const float mn0 = fmaxf(m0, rm0), mn1 = fmaxf(m1, rm1);
        const float a0 = __expf(m0 - mn0), a1 = __expf(m1 - mn1);
        m0 = mn0; m1 = mn1;

        float ps0 = 0.f, ps1 = 0.f;
        const int prow0 = (rowgrp * 16 + lq) * P_STR;
        const int prow1 = prow0 + 8 * P_STR;
        #pragma unroll
        for (int nf = 0; nf < 4; nf++) {
            const int c0 = ksplit * 32 + nf * 8 + 2 * lr;
            float p00 = __expf(sacc[nf][0] - mn0);
            float p01 = __expf(sacc[nf][1] - mn0);
            float p10 = __expf(sacc[nf][2] - mn1);
            float p11 = __expf(sacc[nf][3] - mn1);
            ps0 += p00 + p01;
            ps1 += p10 + p11;
            Pu[prow0 + c0]     = f2tf(p00);
            Pu[prow0 + c0 + 1] = f2tf(p01);
            Pu[prow1 + c0]     = f2tf(p10);
            Pu[prow1 + c0 + 1] = f2tf(p11);
        }
        ps0 += __shfl_xor_sync(0xffffffffu, ps0, 1);
        ps0 += __shfl_xor_sync(0xffffffffu, ps0, 2);
        ps1 += __shfl_xor_sync(0xffffffffu, ps1, 1);
        ps1 += __shfl_xor_sync(0xffffffffu, ps1, 2);
        l0 = l0 * a0 + ps0;
        l1 = l1 * a1 + ps1;
        #pragma unroll
        for (int nf = 0; nf < 8; nf++) {
            of[nf][0] *= a0; of[nf][1] *= a0;
            of[nf][2] *= a1; of[nf][3] *= a1;
        }
        __syncwarp();

        // ---- P V over this warp's 32-key slice ----
        #pragma unroll
        for (int kst = 0; kst < 4; kst++) {
            uint32_t pa[4];
            const int pc = ksplit * 32 + kst * 8 + lr;
            pa[0] = Pu[(rowgrp * 16 + lq) * P_STR + pc];
            pa[1] = Pu[(rowgrp * 16 + lq + 8) * P_STR + pc];
            pa[2] = Pu[(rowgrp * 16 + lq) * P_STR + pc + 4];
            pa[3] = Pu[(rowgrp * 16 + lq + 8) * P_STR + pc + 4];
            const int vr = ksplit * 32 + kst * 8 + lr;
            #pragma unroll
            for (int nf = 0; nf < 8; nf++) {
                const int dcol = nf * 8 + lq;
                uint32_t b0 = f2tf(Vb[vr * KV_STR + dcol]);
                uint32_t b1 = f2tf(Vb[(vr + 4) * KV_STR + dcol]);
                mma8(of[nf], pa, b0, b1);
            }
        }

        __syncthreads();
        buf ^= 1;
    }

    // ---- split-K merge (pairs: warps 2g and 2g+1 share 16 q rows) ----
    float* mb = sm + OFF_P + rowgrp * 1152;   // overlays P (+ LUT head), both dead now
    if (ksplit == 1) {
        mb[lane * 4 + 0] = m0;
        mb[lane * 4 + 1] = m1;
        mb[lane * 4 + 2] = l0;
        mb[lane * 4 + 3] = l1;
        float* ob = mb + 128;
        #pragma unroll
        for (int nf = 0; nf < 8; nf++)
            *(float4*)&ob[lane * 32 + nf * 4] =
                make_float4(of[nf][0], of[nf][1], of[nf][2], of[nf][3]);
    }
    __syncthreads();
    if (ksplit == 0) {
        float m0B = mb[lane * 4 + 0], m1B = mb[lane * 4 + 1];
        float l0B = mb[lane * 4 + 2], l1B = mb[lane * 4 + 3];
        const float* ob = mb + 128;
        float M0 = fmaxf(m0, m0B), M1 = fmaxf(m1, m1B);
        float cA0 = __expf(m0 - M0), cB0 = __expf(m0B - M0);
        float cA1 = __expf(m1 - M1), cB1 = __expf(m1B - M1);
        float i0 = __fdividef(1.f, l0 * cA0 + l0B * cB0);
        float i1 = __fdividef(1.f, l1 * cA1 + l1B * cB1);
        const size_t r0 = ((size_t)(b * NQ + q0 + rowgrp * 16 + lq)) * HID_ + h * HD_;
        const size_t r1 = r0 + 8 * HID_;
        #pragma unroll
        for (int nf = 0; nf < 8; nf++) {
            float4 oB = *(const float4*)&ob[lane * 32 + nf * 4];
            const int c = nf * 8 + 2 * lr;
            *(float2*)&g_attn[r0 + c] = make_float2(
                (of[nf][0] * cA0 + oB.x * cB0) * i0,
                (of[nf][1] * cA0 + oB.y * cB0) * i0);
            *(float2*)&g_attn[r1 + c] = make_float2(
                (of[nf][2] * cA1 + oB.z * cB1) * i1,
                (of[nf][3] * cA1 + oB.w * cB1) * i1);
        }
    }
}

// ---------------------------------------------------------------------------
extern "C" void kernel_launch(void* const* d_in, const int* in_sizes, int n_in,
                              void* d_out, int out_size)
{
    const float* q_in      = (const float*)d_in[0];
    const float* kv_in     = (const float*)d_in[1];
    const float* q_coords  = (const float*)d_in[2];
    const float* kv_coords = (const float*)d_in[3];
    const float* Wq        = (const float*)d_in[4];
    const float* Wk        = (const float*)d_in[5];
    const float* Wv        = (const float*)d_in[6];
    const float* Wo        = (const float*)d_in[7];
    const float* W1        = (const float*)d_in[8];
    const float* b1        = (const float*)d_in[9];
    const float* W2        = (const float*)d_in[10];
    const float* b2        = (const float*)d_in[11];
    float* out             = (float*)d_out;

    float *Qp, *Kp, *Vp, *Ap;
    cudaGetSymbolAddress((void**)&Qp, g_Q);
    cudaGetSymbolAddress((void**)&Kp, g_K);
    cudaGetSymbolAddress((void**)&Vp, g_V);
    cudaGetSymbolAddress((void**)&Ap, g_attn);

    static bool attr_set = false;
    if (!attr_set) {
        cudaFuncSetAttribute(attn_kernel,
            cudaFuncAttributeMaxDynamicSharedMemorySize, ATT_SMEM_FLOATS * 4);
        attr_set = true;
    }

    // bias LUT pipeline
    init_kernel<<<1, 32>>>();
    norm_kernel<<<(B_ * NQ + B_ * NK + 255) / 256, 256>>>(q_coords, kv_coords);
    lut_kernel<<<(LUT_T + 255) / 256, 256>>>(W1, b1, W2, b2);

    // Fused Q/K/V projections (TF32 tensor cores)
    gemm_qkv_kernel<<<dim3(HID_ / 64, 80), 256>>>(
        q_in, kv_in, Wq, Wk, Wv, Qp, Kp, Vp);

    // Flash attention (TF32, warp split-K, cp.async pipeline)
    attn_kernel<<<dim3(NQ / 64, H_, B_), 256, ATT_SMEM_FLOATS * 4>>>(q_coords, kv_coords);

    // Output projection
    gemm_kernel<<<dim3(DIM_ / 64, (B_ * NQ) / 128), 256>>>(Ap, Wo, out, DIM_, HID_);
}

// round 6
// speedup vs baseline: 1.0446x; 1.0446x over previous
#include <cuda_runtime.h>
#include <math.h>
#include <stdint.h>

#define B_    2
#define NQ    1024
#define NK    2048
#define DIM_  512
#define HID_  512
#define H_    8
#define HD_   64
#define RBH   64
#define LUT_T 2048

// Static device scratch
__device__ float g_Q[(size_t)B_ * NQ * HID_];
__device__ float g_K[(size_t)B_ * NK * HID_];
__device__ float g_V[(size_t)B_ * NK * HID_];
__device__ float g_attn[(size_t)B_ * NQ * HID_];   // split 0 partial, then merged
__device__ float g_O2[(size_t)B_ * NQ * HID_];     // split 1 partial
__device__ float g_ml[2 * B_ * H_ * NQ * 2];       // [split][b][h][q][m,l]
__device__ float g_lut[H_ * LUT_T];
__device__ unsigned int g_maxbits[2];
__device__ float g_inv_step2;

// ---------------------------------------------------------------------------
__device__ __forceinline__ uint32_t f2tf(float x) {
    uint32_t r; asm("cvt.rna.tf32.f32 %0, %1;" : "=r"(r) : "f"(x)); return r;
}
__device__ __forceinline__ void mma8(float* d, const uint32_t* a, uint32_t b0, uint32_t b1) {
    asm volatile(
        "mma.sync.aligned.m16n8k8.row.col.f32.tf32.tf32.f32 "
        "{%0,%1,%2,%3}, {%4,%5,%6,%7}, {%8,%9}, {%0,%1,%2,%3};"
        : "+f"(d[0]), "+f"(d[1]), "+f"(d[2]), "+f"(d[3])
        : "r"(a[0]), "r"(a[1]), "r"(a[2]), "r"(a[3]), "r"(b0), "r"(b1));
}
__device__ __forceinline__ void cpa16(uint32_t s, const float* g) {
    asm volatile("cp.async.cg.shared.global [%0], [%1], 16;" :: "r"(s), "l"(g));
}
__device__ __forceinline__ uint32_t s2u(const void* p) {
    return (uint32_t)__cvta_generic_to_shared(p);
}

// ---------------------------------------------------------------------------
// LUT pipeline
// ---------------------------------------------------------------------------
__global__ void init_kernel() {
    if (threadIdx.x < 2) g_maxbits[threadIdx.x] = 0u;
}

__global__ __launch_bounds__(256) void norm_kernel(
    const float* __restrict__ qc, const float* __restrict__ kc)
{
    const int NQT = B_ * NQ;
    const int NKT = B_ * NK;
    int i = blockIdx.x * 256 + threadIdx.x;
    float n = 0.f;
    int which = 0;
    if (i < NQT) {
        float x = qc[i*3], y = qc[i*3+1], z = qc[i*3+2];
        n = sqrtf(fmaf(x,x,fmaf(y,y,z*z)));
    } else if (i < NQT + NKT) {
        int j = i - NQT;
        float x = kc[j*3], y = kc[j*3+1], z = kc[j*3+2];
        n = sqrtf(fmaf(x,x,fmaf(y,y,z*z)));
        which = 1;
    }
    atomicMax(&g_maxbits[which], __float_as_uint(n));
}

__global__ __launch_bounds__(256) void lut_kernel(
    const float* __restrict__ W1, const float* __restrict__ b1,
    const float* __restrict__ W2, const float* __restrict__ b2)
{
    __shared__ float sW1[RBH], sb1[RBH], sW2[RBH * H_];
    int t = threadIdx.x;
    if (t < RBH) { sW1[t] = W1[t]; sb1[t] = b1[t]; }
    for (int i = t; i < RBH * H_; i += 256) sW2[i] = W2[i];
    __syncthreads();

    float dmax = __uint_as_float(g_maxbits[0]) + __uint_as_float(g_maxbits[1]) + 1e-3f;
    float step2 = dmax * dmax / (float)(LUT_T - 1);
    if (blockIdx.x == 0 && t == 0) g_inv_step2 = 1.0f / step2;

    int i = blockIdx.x * 256 + t;
    if (i >= LUT_T) return;
    float d = sqrtf(step2 * (float)i);

    float o[H_];
    #pragma unroll
    for (int hh = 0; hh < H_; hh++) o[hh] = b2[hh];
    #pragma unroll 8
    for (int j = 0; j < RBH; j++) {
        float x = fmaf(d, sW1[j], sb1[j]);
        float s = __fdividef(x, 1.0f + __expf(-x));
        #pragma unroll
        for (int hh = 0; hh < H_; hh++)
            o[hh] = fmaf(s, sW2[j * H_ + hh], o[hh]);
    }
    #pragma unroll
    for (int hh = 0; hh < H_; hh++) g_lut[hh * LUT_T + i] = o[hh];
}

// ---------------------------------------------------------------------------
// Big-tile TF32 GEMM for QKV: 128x128x16, 256 thr, 8 warps (4m x 2n, 32x64),
// cp.async double-buffered, cvt at fragment load.
// ---------------------------------------------------------------------------
#define QAS 20
#define QBS 136

__global__ __launch_bounds__(256) void gemm_qkv_kernel(
    const float* __restrict__ q_in, const float* __restrict__ kv_in,
    const float* __restrict__ Wq, const float* __restrict__ Wk,
    const float* __restrict__ Wv,
    float* __restrict__ Qo, float* __restrict__ Ko, float* __restrict__ Vo)
{
    __shared__ float As[2][128 * QAS];
    __shared__ float Bs[2][16 * QBS];

    int by = blockIdx.y;
    const float *A, *Bw; float* C;
    if (by < 16)      { A = q_in;  Bw = Wq; C = Qo; }
    else if (by < 48) { A = kv_in; Bw = Wk; C = Ko; by -= 16; }
    else              { A = kv_in; Bw = Wv; C = Vo; by -= 48; }
    const int row0 = by * 128;
    const int col0 = blockIdx.x * 128;

    const int tid = threadIdx.x;
    const int lane = tid & 31, wid = tid >> 5;
    const int wm = (wid >> 1) * 32, wn = (wid & 1) * 64;
    const int lq = lane >> 2, lr = lane & 3;
    const int ar = tid >> 1, ac = (tid & 1) * 8;
    const int bk = tid >> 4, bn = (tid & 15) * 8;

    float acc[2][8][4] = {};

    auto issue = [&](int k0, int bf) {
        const float* ag = A  + (size_t)(row0 + ar) * DIM_ + k0 + ac;
        const float* bg = Bw + (size_t)(k0 + bk) * HID_ + col0 + bn;
        uint32_t a_s = s2u(&As[bf][ar * QAS + ac]);
        uint32_t b_s = s2u(&Bs[bf][bk * QBS + bn]);
        cpa16(a_s, ag); cpa16(a_s + 16, ag + 4);
        cpa16(b_s, bg); cpa16(b_s + 16, bg + 4);
        asm volatile("cp.async.commit_group;" ::: "memory");
    };

    issue(0, 0);
    int buf = 0;
    for (int k0 = 0; k0 < DIM_; k0 += 16) {
        const bool more = (k0 + 16) < DIM_;
        if (more) {
            issue(k0 + 16, buf ^ 1);
            asm volatile("cp.async.wait_group 1;" ::: "memory");
        } else {
            asm volatile("cp.async.wait_group 0;" ::: "memory");
        }
        __syncthreads();

        const float* Ab = As[buf];
        const float* Bb = Bs[buf];
        #pragma unroll
        for (int s = 0; s < 2; s++) {
            const int kc_ = s * 8 + lr;
            uint32_t af[2][4], bfr[8][2];
            #pragma unroll
            for (int mf = 0; mf < 2; mf++) {
                const int r = wm + mf * 16 + lq;
                af[mf][0] = f2tf(Ab[r * QAS + kc_]);
                af[mf][1] = f2tf(Ab[(r + 8) * QAS + kc_]);
                af[mf][2] = f2tf(Ab[r * QAS + kc_ + 4]);
                af[mf][3] = f2tf(Ab[(r + 8) * QAS + kc_ + 4]);
            }
            #pragma unroll
            for (int nf = 0; nf < 8; nf++) {
                const int cc = wn + nf * 8 + lq;
                bfr[nf][0] = f2tf(Bb[kc_ * QBS + cc]);
                bfr[nf][1] = f2tf(Bb[(kc_ + 4) * QBS + cc]);
            }
            #pragma unroll
            for (int mf = 0; mf < 2; mf++)
                #pragma unroll
                for (int nf = 0; nf < 8; nf++)
                    mma8(acc[mf][nf], af[mf], bfr[nf][0], bfr[nf][1]);
        }
        __syncthreads();
        buf ^= 1;
    }

    #pragma unroll
    for (int mf = 0; mf < 2; mf++)
        #pragma unroll
        for (int nf = 0; nf < 8; nf++) {
            const int r = row0 + wm + mf * 16 + lq;
            const int c = col0 + wn + nf * 8 + 2 * lr;
            *(float2*)&C[(size_t)r * HID_ + c]       = make_float2(acc[mf][nf][0], acc[mf][nf][1]);
            *(float2*)&C[(size_t)(r + 8) * HID_ + c] = make_float2(acc[mf][nf][2], acc[mf][nf][3]);
        }
}

// ---------------------------------------------------------------------------
// Out-proj GEMM (128x64x16, register-staged, known-good from R4/R5)
// ---------------------------------------------------------------------------
#define AS_STR 20
#define BS_STR 72

__global__ __launch_bounds__(256) void gemm_kernel(
    const float* __restrict__ A, const float* __restrict__ Bm,
    float* __restrict__ C, int N, int K)
{
    __shared__ uint32_t As2[2 * 128 * AS_STR];
    __shared__ uint32_t Bs2[2 * 16 * BS_STR];

    const int tid  = threadIdx.x;
    const int lane = tid & 31, wid = tid >> 5;
    const int wm = (wid >> 1) * 32, wn = (wid & 1) * 32;
    const int row0 = blockIdx.y * 128, col0 = blockIdx.x * 64;
    const int lq = lane >> 2, lr = lane & 3;
    const int ar = tid >> 1, ac = (tid & 1) * 8;
    const int bk = tid >> 4, bn = (tid & 15) * 4;

    float acc[2][4][4] = {};

    {
        float4 a0 = *(const float4*)&A[(size_t)(row0 + ar) * K + ac];
        float4 a1 = *(const float4*)&A[(size_t)(row0 + ar) * K + ac + 4];
        float4 b0 = *(const float4*)&Bm[(size_t)bk * N + col0 + bn];
        *(uint4*)&As2[ar * AS_STR + ac]     = make_uint4(f2tf(a0.x), f2tf(a0.y), f2tf(a0.z), f2tf(a0.w));
        *(uint4*)&As2[ar * AS_STR + ac + 4] = make_uint4(f2tf(a1.x), f2tf(a1.y), f2tf(a1.z), f2tf(a1.w));
        *(uint4*)&Bs2[bk * BS_STR + bn]     = make_uint4(f2tf(b0.x), f2tf(b0.y), f2tf(b0.z), f2tf(b0.w));
    }
    __syncthreads();

    int buf = 0;
    for (int k0 = 0; k0 < K; k0 += 16) {
        const bool more = (k0 + 16) < K;
        float4 na0, na1, nb0;
        if (more) {
            na0 = *(const float4*)&A[(size_t)(row0 + ar) * K + k0 + 16 + ac];
            na1 = *(const float4*)&A[(size_t)(row0 + ar) * K + k0 + 16 + ac + 4];
            nb0 = *(const float4*)&Bm[(size_t)(k0 + 16 + bk) * N + col0 + bn];
        }
        const uint32_t* Ab = As2 + buf * (128 * AS_STR);
        const uint32_t* Bb = Bs2 + buf * (16 * BS_STR);

        #pragma unroll
        for (int s = 0; s < 2; s++) {
            uint32_t af[2][4], bfr[4][2];
            const int kc_ = s * 8 + lr;
            #pragma unroll
            for (int mf = 0; mf < 2; mf++) {
                const int r = wm + mf * 16 + lq;
                af[mf][0] = Ab[r * AS_STR + kc_];
                af[mf][1] = Ab[(r + 8) * AS_STR + kc_];
                af[mf][2] = Ab[r * AS_STR + kc_ + 4];
                af[mf][3] = Ab[(r + 8) * AS_STR + kc_ + 4];
            }
            #pragma unroll
            for (int nf = 0; nf < 4; nf++) {
                const int cc = wn + nf * 8 + lq;
                bfr[nf][0] = Bb[kc_ * BS_STR + cc];
                bfr[nf][1] = Bb[(kc_ + 4) * BS_STR + cc];
            }
            #pragma unroll
            for (int mf = 0; mf < 2; mf++)
                #pragma unroll
                for (int nf = 0; nf < 4; nf++)
                    mma8(acc[mf][nf], af[mf], bfr[nf][0], bfr[nf][1]);
        }

        if (more) {
            buf ^= 1;
            uint32_t* Aw = As2 + buf * (128 * AS_STR);
            uint32_t* Bw = Bs2 + buf * (16 * BS_STR);
            *(uint4*)&Aw[ar * AS_STR + ac]     = make_uint4(f2tf(na0.x), f2tf(na0.y), f2tf(na0.z), f2tf(na0.w));
            *(uint4*)&Aw[ar * AS_STR + ac + 4] = make_uint4(f2tf(na1.x), f2tf(na1.y), f2tf(na1.z), f2tf(na1.w));
            *(uint4*)&Bw[bk * BS_STR + bn]     = make_uint4(f2tf(nb0.x), f2tf(nb0.y), f2tf(nb0.z), f2tf(nb0.w));
            __syncthreads();
        }
    }

    #pragma unroll
    for (int mf = 0; mf < 2; mf++)
        #pragma unroll
        for (int nf = 0; nf < 4; nf++) {
            const int r = row0 + wm + mf * 16 + lq;
            const int c = col0 + wn + nf * 8 + 2 * lr;
            *(float2*)&C[(size_t)r * N + c]       = make_float2(acc[mf][nf][0], acc[mf][nf][1]);
            *(float2*)&C[(size_t)(r + 8) * N + c] = make_float2(acc[mf][nf][2], acc[mf][nf][3]);
        }
}

// ---------------------------------------------------------------------------
// TF32 flash attention, CTA split-K. CTA = 64 q x 1024 keys, 128 thr/4 warps.
// d^2 computed via extended-K mma. K/V double-buffered via cp.async.
// ---------------------------------------------------------------------------
#define KV_STR 76   // K tile: 64 data cols + 8 ext cols, stride 76 (conflict-free)
#define V_STR  72
#define P_STR  68
// float offsets
#define OFF_K   0                       // 2 * 64 * 76 = 9728
#define OFF_V   9728                    // 2 * 64 * 72 = 9216
#define OFF_P   18944                   // 64 * 68 = 4352
#define OFF_LUT 23296                   // 2048
#define ATT_SMEM_FLOATS 25344           // * 4 = 101376 B

__global__ __launch_bounds__(128) void attn_kernel(
    const float* __restrict__ qc, const float* __restrict__ kc)
{
    extern __shared__ float sm[];
    float*    slut = sm + OFF_LUT;
    uint32_t* Pu   = (uint32_t*)(sm + OFF_P);

    const int b   = blockIdx.z >> 1;
    const int ks  = blockIdx.z & 1;
    const int h   = blockIdx.y;
    const int q0  = blockIdx.x * 64;
    const int tid = threadIdx.x;
    const int lane = tid & 31;
    const int w    = tid >> 5;           // 0..3, warp owns 16 q rows
    const int lq   = lane >> 2;
    const int lr   = lane & 3;
    const int kstart = ks * (NK / 2);

    // zero ext padding cols 68-71 (both buffers), once
    {
        int bf = tid >> 6, key = tid & 63;
        float* z = sm + OFF_K + bf * 4864 + key * KV_STR + 68;
        z[0] = 0.f; z[1] = 0.f; z[2] = 0.f; z[3] = 0.f;
    }
    // stage LUT
    for (int i = tid; i < LUT_T; i += 128) slut[i] = g_lut[h * LUT_T + i];
    const float inv_step2 = g_inv_step2;

    // Q fragments (scale folded) + coord fragment
    uint32_t qa[8][4], qa2[4];
    float qn2s0, qn2s1;
    {
        const size_t r0 = ((size_t)(b * NQ + q0 + w * 16 + lq)) * HID_ + h * HD_;
        const size_t r1 = r0 + 8 * HID_;
        #pragma unroll
        for (int kss = 0; kss < 8; kss++) {
            qa[kss][0] = f2tf(0.125f * g_Q[r0 + kss * 8 + lr]);
            qa[kss][1] = f2tf(0.125f * g_Q[r1 + kss * 8 + lr]);
            qa[kss][2] = f2tf(0.125f * g_Q[r0 + kss * 8 + lr + 4]);
            qa[kss][3] = f2tf(0.125f * g_Q[r1 + kss * 8 + lr + 4]);
        }
        const float* p0 = qc + ((size_t)b * NQ + q0 + w * 16 + lq) * 3;
        const float* p1 = p0 + 8 * 3;
        float c0[4] = {p0[0], p0[1], p0[2], 1.0f};
        float c1[4] = {p1[0], p1[1], p1[2], 1.0f};
        qa2[0] = f2tf(c0[lr]);
        qa2[1] = f2tf(c1[lr]);
        qa2[2] = 0u; qa2[3] = 0u;
        qn2s0 = fmaf(c0[0], c0[0], fmaf(c0[1], c0[1], c0[2] * c0[2])) * inv_step2;
        qn2s1 = fmaf(c1[0], c1[0], fmaf(c1[1], c1[1], c1[2] * c1[2])) * inv_step2;
    }

    float of[8][4] = {};
    float m0 = -INFINITY, m1 = -INFINITY, l0 = 0.f, l1 = 0.f;

    const float* Kp  = g_K + ((size_t)b * NK) * HID_ + h * HD_;
    const float* Vp  = g_V + ((size_t)b * NK) * HID_ + h * HD_;
    const float* kcb = kc + (size_t)b * NK * 3;

    const int lkey = tid >> 1;          // 0..63
    const int half = (tid & 1) * 32;

    auto issue = [&](int t, int bf) {
        const size_t kg = (size_t)(kstart + t * 64 + lkey) * HID_ + half;
        uint32_t kd = s2u(sm + OFF_K + bf * 4864 + lkey * KV_STR + half);
        uint32_t vd = s2u(sm + OFF_V + bf * 4608 + lkey * V_STR + half);
        #pragma unroll
        for (int u = 0; u < 8; u++) cpa16(kd + u * 16, Kp + kg + u * 4);
        #pragma unroll
        for (int u = 0; u < 8; u++) cpa16(vd + u * 16, Vp + kg + u * 4);
        asm volatile("cp.async.commit_group;" ::: "memory");
    };

    // per-thread coord prefetch (tid<64 handles key tid of current tile)
    float ccx = 0.f, ccy = 0.f, ccz = 0.f;
    if (tid < 64) {
        const float* p = kcb + (size_t)(kstart + tid) * 3;
        ccx = p[0]; ccy = p[1]; ccz = p[2];
    }

    issue(0, 0);
    int buf = 0;
    const int NT = (NK / 2) / 64;

    for (int t = 0; t < NT; t++) {
        const bool more = (t + 1) < NT;
        if (more) {
            issue(t + 1, buf ^ 1);
            asm volatile("cp.async.wait_group 1;" ::: "memory");
        } else {
            asm volatile("cp.async.wait_group 0;" ::: "memory");
        }
        // write ext cols for current tile from registers (no cross-thread dep)
        if (tid < 64) {
            float* ext = sm + OFF_K + buf * 4864 + tid * KV_STR + 64;
            ext[0] = -2.f * ccx * inv_step2;
            ext[1] = -2.f * ccy * inv_step2;
            ext[2] = -2.f * ccz * inv_step2;
            ext[3] = fmaf(ccx, ccx, fmaf(ccy, ccy, ccz * ccz)) * inv_step2;
        }
        __syncthreads();
        // prefetch next tile coords (latency hidden by compute)
        if (more && tid < 64) {
            const float* p = kcb + (size_t)(kstart + (t + 1) * 64 + tid) * 3;
            ccx = __ldg(p); ccy = __ldg(p + 1); ccz = __ldg(p + 2);
        }

        const float* Kb = sm + OFF_K + buf * 4864;
        const float* Vb = sm + OFF_V + buf * 4608;

        // ---- QK^T ----
        float sacc[8][4] = {};
        #pragma unroll
        for (int kss = 0; kss < 8; kss++) {
            const int dcol = kss * 8 + lr;
            #pragma unroll
            for (int nf = 0; nf < 8; nf++) {
                const int key = nf * 8 + lq;
                uint32_t b0 = f2tf(Kb[key * KV_STR + dcol]);
                uint32_t b1 = f2tf(Kb[key * KV_STR + dcol + 4]);
                mma8(sacc[nf], qa[kss], b0, b1);
            }
        }
        // ---- d^2 * inv_step2 via ext mma ----
        float dd[8][4] = {};
        #pragma unroll
        for (int nf = 0; nf < 8; nf++) {
            uint32_t be = f2tf(Kb[(nf * 8 + lq) * KV_STR + 64 + lr]);
            mma8(dd[nf], qa2, be, 0u);
        }

        // ---- bias + online softmax ----
        float rm0 = -INFINITY, rm1 = -INFINITY;
        #pragma unroll
        for (int nf = 0; nf < 8; nf++) {
            {
                float u = dd[nf][0] + qn2s0;
                int ii = (int)u; ii = min(max(ii, 0), LUT_T - 2);
                float fr = u - (float)ii;
                sacc[nf][0] += fmaf(fr, slut[ii+1] - slut[ii], slut[ii]);
            }
            {
                float u = dd[nf][1] + qn2s0;
                int ii = (int)u; ii = min(max(ii, 0), LUT_T - 2);
                float fr = u - (float)ii;
                sacc[nf][1] += fmaf(fr, slut[ii+1] - slut[ii], slut[ii]);
            }
            {
                float u = dd[nf][2] + qn2s1;
                int ii = (int)u; ii = min(max(ii, 0), LUT_T - 2);
                float fr = u - (float)ii;
                sacc[nf][2] += fmaf(fr, slut[ii+1] - slut[ii], slut[ii]);
            }
            {
                float u = dd[nf][3] + qn2s1;
                int ii = (int)u; ii = min(max(ii, 0), LUT_T - 2);
                float fr = u - (float)ii;
                sacc[nf][3] += fmaf(fr, slut[ii+1] - slut[ii], slut[ii]);
            }
            rm0 = fmaxf(rm0, fmaxf(sacc[nf][0], sacc[nf][1]));
            rm1 = fmaxf(rm1, fmaxf(sacc[nf][2], sacc[nf][3]));
        }
        rm0 = fmaxf(rm0, __shfl_xor_sync(0xffffffffu, rm0, 1));
        rm0 = fmaxf(rm0, __shfl_xor_sync(0xffffffffu, rm0, 2));
        rm1 = fmaxf(rm1, __shfl_xor_sync(0xffffffffu, rm1, 1));
        rm1 = fmaxf(rm1, __shfl_xor_sync(0xffffffffu, rm1, 2));

        const float mn0 = fmaxf(m0, rm0), mn1 = fmaxf(m1, rm1);
        const float a0 = __expf(m0 - mn0), a1 = __expf(m1 - mn1);
        m0 = mn0; m1 = mn1;

        float ps0 = 0.f, ps1 = 0.f;
        const int prow0 = (w * 16 + lq) * P_STR;
        const int prow1 = prow0 + 8 * P_STR;
        #pragma unroll
        for (int nf = 0; nf < 8; nf++) {
            const int c0 = nf * 8 + 2 * lr;
            float p00 = __expf(sacc[nf][0] - mn0);
            float p01 = __expf(sacc[nf][1] - mn0);
            float p10 = __expf(sacc[nf][2] - mn1);
            float p11 = __expf(sacc[nf][3] - mn1);
            ps0 += p00 + p01;
            ps1 += p10 + p11;
            Pu[prow0 + c0]     = f2tf(p00);
            Pu[prow0 + c0 + 1] = f2tf(p01);
            Pu[prow1 + c0]     = f2tf(p10);
            Pu[prow1 + c0 + 1] = f2tf(p11);
        }
        ps0 += __shfl_xor_sync(0xffffffffu, ps0, 1);
        ps0 += __shfl_xor_sync(0xffffffffu, ps0, 2);
        ps1 += __shfl_xor_sync(0xffffffffu, ps1, 1);
        ps1 += __shfl_xor_sync(0xffffffffu, ps1, 2);
        l0 = l0 * a0 + ps0;
        l1 = l1 * a1 + ps1;
        #pragma unroll
        for (int nf = 0; nf < 8; nf++) {
            of[nf][0] *= a0; of[nf][1] *= a0;
            of[nf][2] *= a1; of[nf][3] *= a1;
        }
        __syncwarp();

        // ---- P V ----
        #pragma unroll
        for (int kst = 0; kst < 8; kst++) {
            uint32_t pa[4];
            const int pc = kst * 8 + lr;
            pa[0] = Pu[(w * 16 + lq) * P_STR + pc];
            pa[1] = Pu[(w * 16 + lq + 8) * P_STR + pc];
            pa[2] = Pu[(w * 16 + lq) * P_STR + pc + 4];
            pa[3] = Pu[(w * 16 + lq + 8) * P_STR + pc + 4];
            #pragma unroll
            for (int nf = 0; nf < 8; nf++) {
                const int dcol = nf * 8 + lq;
                uint32_t b0 = f2tf(Vb[(kst * 8 + lr) * V_STR + dcol]);
                uint32_t b1 = f2tf(Vb[(kst * 8 + lr + 4) * V_STR + dcol]);
                mma8(of[nf], pa, b0, b1);
            }
        }

        __syncthreads();
        buf ^= 1;
    }

    // epilogue: write unnormalized partial + (m,l)
    float* pO = ks ? g_O2 : g_attn;
    const size_t r0 = ((size_t)(b * NQ + q0 + w * 16 + lq)) * HID_ + h * HD_;
    const size_t r1 = r0 + 8 * HID_;
    #pragma unroll
    for (int nf = 0; nf < 8; nf++) {
        const int c = nf * 8 + 2 * lr;
        *(float2*)&pO[r0 + c] = make_float2(of[nf][0], of[nf][1]);
        *(float2*)&pO[r1 + c] = make_float2(of[nf][2], of[nf][3]);
    }
    if (lr == 0) {
        const size_t base = (((size_t)ks * B_ + b) * H_ + h) * NQ;
        const int qr = q0 + w * 16 + lq;
        g_ml[(base + qr) * 2]     = m0;
        g_ml[(base + qr) * 2 + 1] = l0;
        g_ml[(base + qr + 8) * 2]     = m1;
        g_ml[(base + qr + 8) * 2 + 1] = l1;
    }
}

// ---------------------------------------------------------------------------
// Split-K merge: O = (O_A*cA + O_B*cB) / (lA*cA + lB*cB), in place into g_attn
// ---------------------------------------------------------------------------
__global__ __launch_bounds__(512) void merge_kernel()
{
    const int row = blockIdx.x;              // b*NQ + q
    const int b = row >> 10;                 // NQ = 1024
    const int q = row & 1023;
    const int c = threadIdx.x;               // 0..511
    const int h = c >> 6;

    const size_t iA = ((((size_t)0 * B_ + b) * H_ + h) * NQ + q) * 2;
    const size_t iB = ((((size_t)1 * B_ + b) * H_ + h) * NQ + q) * 2;
    const float mA = g_ml[iA], lA = g_ml[iA + 1];
    const float mB = g_ml[iB], lB = g_ml[iB + 1];
    const float M  = fmaxf(mA, mB);
    const float cA = __expf(mA - M), cB = __expf(mB - M);
    const float inv = __fdividef(1.f, fmaf(lA, cA, lB * cB));

    const size_t o = (size_t)row * HID_ + c;
    g_attn[o] = (g_attn[o] * cA + g_O2[o] * cB) * inv;
}

// ---------------------------------------------------------------------------
extern "C" void kernel_launch(void* const* d_in, const int* in_sizes, int n_in,
                              void* d_out, int out_size)
{
    const float* q_in      = (const float*)d_in[0];
    const float* kv_in     = (const float*)d_in[1];
    const float* q_coords  = (const float*)d_in[2];
    const float* kv_coords = (const float*)d_in[3];
    const float* Wq        = (const float*)d_in[4];
    const float* Wk        = (const float*)d_in[5];
    const float* Wv        = (const float*)d_in[6];
    const float* Wo        = (const float*)d_in[7];
    const float* W1        = (const float*)d_in[8];
    const float* b1        = (const float*)d_in[9];
    const float* W2        = (const float*)d_in[10];
    const float* b2        = (const float*)d_in[11];
    float* out             = (float*)d_out;

    float *Qp, *Kp, *Vp, *Ap;
    cudaGetSymbolAddress((void**)&Qp, g_Q);
    cudaGetSymbolAddress((void**)&Kp, g_K);
    cudaGetSymbolAddress((void**)&Vp, g_V);
    cudaGetSymbolAddress((void**)&Ap, g_attn);

    static bool attr_set = false;
    if (!attr_set) {
        cudaFuncSetAttribute(attn_kernel,
            cudaFuncAttributeMaxDynamicSharedMemorySize, ATT_SMEM_FLOATS * 4);
        attr_set = true;
    }

    // bias LUT pipeline
    init_kernel<<<1, 32>>>();
    norm_kernel<<<(B_ * NQ + B_ * NK + 255) / 256, 256>>>(q_coords, kv_coords);
    lut_kernel<<<(LUT_T + 255) / 256, 256>>>(W1, b1, W2, b2);

    // Fused Q/K/V projections (TF32, 128x128, cp.async)
    gemm_qkv_kernel<<<dim3(HID_ / 128, 80), 256>>>(
        q_in, kv_in, Wq, Wk, Wv, Qp, Kp, Vp);

    // Flash attention: CTA split-K, d^2-via-mma bias
    attn_kernel<<<dim3(NQ / 64, H_, B_ * 2), 128, ATT_SMEM_FLOATS * 4>>>(
        q_coords, kv_coords);

    // Merge split-K partials (in place into g_attn)
    merge_kernel<<<B_ * NQ, 512>>>();

    // Output projection
    gemm_kernel<<<dim3(DIM_ / 64, (B_ * NQ) / 128), 256>>>(Ap, Wo, out, DIM_, HID_);
}

// round 7
// speedup vs baseline: 1.2571x; 1.2034x over previous
#include <cuda_runtime.h>
#include <math.h>
#include <stdint.h>

#define B_    2
#define NQ    1024
#define NK    2048
#define DIM_  512
#define HID_  512
#define H_    8
#define HD_   64
#define RBH   64
#define LUT_T 2048
#define LOG2E 1.4426950408889634f

// Static device scratch
__device__ float g_Q[(size_t)B_ * NQ * HID_];      // tf32-pattern, pre-scaled by 0.125*log2e
__device__ float g_K[(size_t)B_ * NK * HID_];      // tf32-pattern
__device__ float g_V[(size_t)B_ * NK * HID_];      // tf32-pattern
__device__ float g_attn[(size_t)B_ * NQ * HID_];   // split-0 partial -> merged (tf32-pattern)
__device__ float g_O2[(size_t)B_ * NQ * HID_];     // split-1 partial
__device__ float g_l[2 * B_ * H_ * NQ];            // [split][b][h][q] softmax denom
__device__ float g_lut[H_ * LUT_T];                // bias(d^2) * log2e
__device__ unsigned int g_maxbits[2];
__device__ float g_inv_step2;

// tf32-pattern copies of harness inputs
__device__ float g_QinT[(size_t)B_ * NQ * DIM_];
__device__ float g_KvT[(size_t)B_ * NK * DIM_];
__device__ float g_WqT[DIM_ * HID_];
__device__ float g_WkT[DIM_ * HID_];
__device__ float g_WvT[DIM_ * HID_];
__device__ float g_WoT[HID_ * DIM_];

// ---------------------------------------------------------------------------
__device__ __forceinline__ uint32_t f2tf(float x) {
    uint32_t r; asm("cvt.rna.tf32.f32 %0, %1;" : "=r"(r) : "f"(x)); return r;
}
__device__ __forceinline__ float ex2(float x) {
    float y; asm("ex2.approx.f32 %0, %1;" : "=f"(y) : "f"(x)); return y;
}
__device__ __forceinline__ void mma8(float* d, const uint32_t* a, uint32_t b0, uint32_t b1) {
    asm volatile(
        "mma.sync.aligned.m16n8k8.row.col.f32.tf32.tf32.f32 "
        "{%0,%1,%2,%3}, {%4,%5,%6,%7}, {%8,%9}, {%0,%1,%2,%3};"
        : "+f"(d[0]), "+f"(d[1]), "+f"(d[2]), "+f"(d[3])
        : "r"(a[0]), "r"(a[1]), "r"(a[2]), "r"(a[3]), "r"(b0), "r"(b1));
}
__device__ __forceinline__ void cpa16(uint32_t s, const float* g) {
    asm volatile("cp.async.cg.shared.global [%0], [%1], 16;" :: "r"(s), "l"(g));
}
__device__ __forceinline__ uint32_t s2u(const void* p) {
    return (uint32_t)__cvta_generic_to_shared(p);
}
__device__ __forceinline__ uint32_t ldr(const float* p) {   // raw bits
    return __float_as_uint(*p);
}

// ---------------------------------------------------------------------------
// LUT pipeline
// ---------------------------------------------------------------------------
__global__ void init_kernel() {
    if (threadIdx.x < 2) g_maxbits[threadIdx.x] = 0u;
}

__global__ __launch_bounds__(256) void norm_kernel(
    const float* __restrict__ qc, const float* __restrict__ kc)
{
    const int NQT = B_ * NQ;
    const int NKT = B_ * NK;
    int i = blockIdx.x * 256 + threadIdx.x;
    float n = 0.f;
    int which = 0;
    if (i < NQT) {
        float x = qc[i*3], y = qc[i*3+1], z = qc[i*3+2];
        n = sqrtf(fmaf(x,x,fmaf(y,y,z*z)));
    } else if (i < NQT + NKT) {
        int j = i - NQT;
        float x = kc[j*3], y = kc[j*3+1], z = kc[j*3+2];
        n = sqrtf(fmaf(x,x,fmaf(y,y,z*z)));
        which = 1;
    }
    atomicMax(&g_maxbits[which], __float_as_uint(n));
}

__global__ __launch_bounds__(256) void lut_kernel(
    const float* __restrict__ W1, const float* __restrict__ b1,
    const float* __restrict__ W2, const float* __restrict__ b2)
{
    __shared__ float sW1[RBH], sb1[RBH], sW2[RBH * H_];
    int t = threadIdx.x;
    if (t < RBH) { sW1[t] = W1[t]; sb1[t] = b1[t]; }
    for (int i = t; i < RBH * H_; i += 256) sW2[i] = W2[i];
    __syncthreads();

    float dmax = __uint_as_float(g_maxbits[0]) + __uint_as_float(g_maxbits[1]) + 1e-3f;
    float step2 = dmax * dmax / (float)(LUT_T - 1);
    if (blockIdx.x == 0 && t == 0) g_inv_step2 = 1.0f / step2;

    int i = blockIdx.x * 256 + t;
    if (i >= LUT_T) return;
    float d = sqrtf(step2 * (float)i);

    float o[H_];
    #pragma unroll
    for (int hh = 0; hh < H_; hh++) o[hh] = b2[hh];
    #pragma unroll 8
    for (int j = 0; j < RBH; j++) {
        float x = fmaf(d, sW1[j], sb1[j]);
        float s = __fdividef(x, 1.0f + __expf(-x));
        #pragma unroll
        for (int hh = 0; hh < H_; hh++)
            o[hh] = fmaf(s, sW2[j * H_ + hh], o[hh]);
    }
    #pragma unroll
    for (int hh = 0; hh < H_; hh++)
        g_lut[hh * LUT_T + i] = o[hh] * LOG2E;   // fold log2(e)
}

// ---------------------------------------------------------------------------
// Convert harness inputs to tf32 bit patterns (float4 grid: 1048576 total)
// ---------------------------------------------------------------------------
__global__ __launch_bounds__(256) void conv_kernel(
    const float4* __restrict__ qin, const float4* __restrict__ kvin,
    const float4* __restrict__ wq, const float4* __restrict__ wk,
    const float4* __restrict__ wv, const float4* __restrict__ wo)
{
    int i = blockIdx.x * 256 + threadIdx.x;
    float4 v; float4* dst;
    if      (i < 262144) { v = qin[i];            dst = (float4*)g_QinT + i; }
    else if (i < 786432) { v = kvin[i - 262144];  dst = (float4*)g_KvT + (i - 262144); }
    else if (i < 851968) { v = wq[i - 786432];    dst = (float4*)g_WqT + (i - 786432); }
    else if (i < 917504) { v = wk[i - 851968];    dst = (float4*)g_WkT + (i - 851968); }
    else if (i < 983040) { v = wv[i - 917504];    dst = (float4*)g_WvT + (i - 917504); }
    else                 { v = wo[i - 983040];    dst = (float4*)g_WoT + (i - 983040); }
    v.x = __uint_as_float(f2tf(v.x));
    v.y = __uint_as_float(f2tf(v.y));
    v.z = __uint_as_float(f2tf(v.z));
    v.w = __uint_as_float(f2tf(v.w));
    *dst = v;
}

// ---------------------------------------------------------------------------
// Raw-tf32 GEMM body: 128xBN tile, BK=16, 3-stage cp.async, 256 thr, 8 warps.
// A,B already tf32 bit patterns. mode: 0 plain store, 1 f2tf, 2 f2tf(x*QSC)
// ---------------------------------------------------------------------------
#define QSC (0.125f * LOG2E)

template<int BN>
__device__ __forceinline__ void gemm_raw_body(
    const float* __restrict__ A, const float* __restrict__ Bm,
    float* __restrict__ C, int N, int K, int row0, int mode, float* sm)
{
    constexpr int BSr = BN + 8;
    constexpr int ASZ = 128 * 20, BSZ = 16 * BSr;
    constexpr int NF  = BN / 16;
    float* As = sm;
    float* Bs = sm + 3 * ASZ;

    const int tid = threadIdx.x;
    const int lane = tid & 31, wid = tid >> 5;
    const int wm = (wid >> 1) * 32, wn = (wid & 1) * (BN / 2);
    const int col0 = blockIdx.x * BN;
    const int lq = lane >> 2, lr = lane & 3;
    const int ar = tid >> 1, ac = (tid & 1) * 8;
    const int bk = tid >> 4, bn = (tid & 15) * (BN / 16);

    float acc[2][NF][4] = {};

    auto issue = [&](int k0) {
        const int st = (k0 >> 4) % 3;
        uint32_t a_s = s2u(&As[st * ASZ + ar * 20 + ac]);
        const float* ag = A + (size_t)(row0 + ar) * K + k0 + ac;
        cpa16(a_s, ag); cpa16(a_s + 16, ag + 4);
        uint32_t b_s = s2u(&Bs[st * BSZ + bk * BSr + bn]);
        const float* bg = Bm + (size_t)(k0 + bk) * N + col0 + bn;
        cpa16(b_s, bg);
        if (BN == 128) cpa16(b_s + 16, bg + 4);
        asm volatile("cp.async.commit_group;" ::: "memory");
    };

    issue(0); issue(16);

    for (int k0 = 0; k0 < K; k0 += 16) {
        if (k0 + 32 < K) {
            asm volatile("cp.async.wait_group 1;" ::: "memory");
            __syncthreads();
            issue(k0 + 32);
        } else if (k0 + 16 < K) {
            asm volatile("cp.async.wait_group 1;" ::: "memory");
            __syncthreads();
        } else {
            asm volatile("cp.async.wait_group 0;" ::: "memory");
            __syncthreads();
        }
        const int st = (k0 >> 4) % 3;
        const float* Ab = As + st * ASZ;
        const float* Bb = Bs + st * BSZ;

        #pragma unroll
        for (int s = 0; s < 2; s++) {
            const int kc_ = s * 8 + lr;
            uint32_t af[2][4], bfr[NF][2];
            #pragma unroll
            for (int mf = 0; mf < 2; mf++) {
                const int r = wm + mf * 16 + lq;
                af[mf][0] = ldr(&Ab[r * 20 + kc_]);
                af[mf][1] = ldr(&Ab[(r + 8) * 20 + kc_]);
                af[mf][2] = ldr(&Ab[r * 20 + kc_ + 4]);
                af[mf][3] = ldr(&Ab[(r + 8) * 20 + kc_ + 4]);
            }
            #pragma unroll
            for (int nf = 0; nf < NF; nf++) {
                const int cc = wn + nf * 8 + lq;
                bfr[nf][0] = ldr(&Bb[kc_ * BSr + cc]);
                bfr[nf][1] = ldr(&Bb[(kc_ + 4) * BSr + cc]);
            }
            #pragma unroll
            for (int mf = 0; mf < 2; mf++)
                #pragma unroll
                for (int nf = 0; nf < NF; nf++)
                    mma8(acc[mf][nf], af[mf], bfr[nf][0], bfr[nf][1]);
        }
    }

    #pragma unroll
    for (int mf = 0; mf < 2; mf++)
        #pragma unroll
        for (int nf = 0; nf < NF; nf++) {
            const int r = row0 + wm + mf * 16 + lq;
            const int c = col0 + wn + nf * 8 + 2 * lr;
            float v[4] = {acc[mf][nf][0], acc[mf][nf][1], acc[mf][nf][2], acc[mf][nf][3]};
            if (mode == 1) {
                #pragma unroll
                for (int u = 0; u < 4; u++) v[u] = __uint_as_float(f2tf(v[u]));
            } else if (mode == 2) {
                #pragma unroll
                for (int u = 0; u < 4; u++) v[u] = __uint_as_float(f2tf(v[u] * QSC));
            }
            *(float2*)&C[(size_t)r * N + c]       = make_float2(v[0], v[1]);
            *(float2*)&C[(size_t)(r + 8) * N + c] = make_float2(v[2], v[3]);
        }
}

// QKV fused: blockIdx.y [0,16)->Q(mode2), [16,48)->K(mode1), [48,80)->V(mode1)
__global__ __launch_bounds__(256, 2) void gemm_qkv_kernel()
{
    extern __shared__ float gsm[];
    int by = blockIdx.y;
    const float *A, *Bw; float* C; int mode;
    if (by < 16)      { A = g_QinT; Bw = g_WqT; C = g_Q; mode = 2; }
    else if (by < 48) { A = g_KvT;  Bw = g_WkT; C = g_K; mode = 1; by -= 16; }
    else              { A = g_KvT;  Bw = g_WvT; C = g_V; mode = 1; by -= 48; }
    gemm_raw_body<128>(A, Bw, C, HID_, DIM_, by * 128, mode, gsm);
}

// Out projection: A = g_attn (tf32-pattern), B = g_WoT, plain fp32 out
__global__ __launch_bounds__(256, 2) void gemm_out_kernel(float* __restrict__ out)
{
    extern __shared__ float gsm[];
    gemm_raw_body<64>(g_attn, g_WoT, out, DIM_, HID_, blockIdx.y * 128, 0, gsm);
}

// ---------------------------------------------------------------------------
// TF32 flash attention, CTA split-K(2), no-max softmax, zero in-loop cvt
// except P. CTA = 64 q x 1024 keys, 128 thr / 4 warps, 32-key tiles.
// ---------------------------------------------------------------------------
#define AKT    32
#define KV_STR 76    // 64 data + 4 ext (d^2 cols) + pad
#define V_STR  72
#define P_STR  36
#define KBUF   (AKT * KV_STR)   // 2432
#define VBUF   (AKT * V_STR)    // 2304
// float offsets
#define OFF_K   0                        // 2 * 2432 = 4864
#define OFF_V   4864                     // 2 * 2304 = 4608
#define OFF_P   9472                     // 64 * 36 = 2304
#define OFF_LUT 11776                    // 2048
#define ATT_SMEM_FLOATS 13824            // * 4 = 55296 B

__global__ __launch_bounds__(128, 3) void attn_kernel(
    const float* __restrict__ qc, const float* __restrict__ kc)
{
    extern __shared__ float sm[];
    float*    slut = sm + OFF_LUT;
    uint32_t* Pu   = (uint32_t*)(sm + OFF_P);

    const int b   = blockIdx.z >> 1;
    const int ks  = blockIdx.z & 1;
    const int h   = blockIdx.y;
    const int q0  = blockIdx.x * 64;
    const int tid = threadIdx.x;
    const int lane = tid & 31;
    const int w    = tid >> 5;
    const int lq   = lane >> 2;
    const int lr   = lane & 3;
    const int kstart = ks * (NK / 2);

    for (int i = tid; i < LUT_T; i += 128) slut[i] = g_lut[h * LUT_T + i];
    const float inv_step2 = g_inv_step2;

    // Q fragments: raw bits (g_Q is pre-scaled, tf32-rounded)
    uint32_t qa[8][4], qa2[4];
    float qn2s0, qn2s1;
    {
        const size_t r0 = ((size_t)(b * NQ + q0 + w * 16 + lq)) * HID_ + h * HD_;
        const size_t r1 = r0 + 8 * HID_;
        #pragma unroll
        for (int kss = 0; kss < 8; kss++) {
            qa[kss][0] = ldr(&g_Q[r0 + kss * 8 + lr]);
            qa[kss][1] = ldr(&g_Q[r1 + kss * 8 + lr]);
            qa[kss][2] = ldr(&g_Q[r0 + kss * 8 + lr + 4]);
            qa[kss][3] = ldr(&g_Q[r1 + kss * 8 + lr + 4]);
        }
        const float* p0 = qc + ((size_t)b * NQ + q0 + w * 16 + lq) * 3;
        const float* p1 = p0 + 8 * 3;
        float c0[4] = {p0[0], p0[1], p0[2], 1.0f};
        float c1[4] = {p1[0], p1[1], p1[2], 1.0f};
        qa2[0] = f2tf(c0[lr]);
        qa2[1] = f2tf(c1[lr]);
        qa2[2] = 0u; qa2[3] = 0u;
        qn2s0 = fmaf(c0[0], c0[0], fmaf(c0[1], c0[1], c0[2] * c0[2])) * inv_step2;
        qn2s1 = fmaf(c1[0], c1[0], fmaf(c1[1], c1[1], c1[2] * c1[2])) * inv_step2;
    }

    float of[8][4] = {};
    float l0 = 0.f, l1 = 0.f;

    const float* Kp  = g_K + ((size_t)b * NK) * HID_ + h * HD_;
    const float* Vp  = g_V + ((size_t)b * NK) * HID_ + h * HD_;
    const float* kcb = kc + (size_t)b * NK * 3;

    const int lkey = tid >> 2;          // 0..31
    const int qo   = (tid & 3) * 16;

    auto issue = [&](int t, int bf) {
        const size_t kg = (size_t)(kstart + t * AKT + lkey) * HID_ + qo;
        uint32_t kd = s2u(sm + OFF_K + bf * KBUF + lkey * KV_STR + qo);
        uint32_t vd = s2u(sm + OFF_V + bf * VBUF + lkey * V_STR + qo);
        #pragma unroll
        for (int u = 0; u < 4; u++) cpa16(kd + u * 16, Kp + kg + u * 4);
        #pragma unroll
        for (int u = 0; u < 4; u++) cpa16(vd + u * 16, Vp + kg + u * 4);
        asm volatile("cp.async.commit_group;" ::: "memory");
    };

    float ccx = 0.f, ccy = 0.f, ccz = 0.f;
    if (tid < AKT) {
        const float* p = kcb + (size_t)(kstart + tid) * 3;
        ccx = p[0]; ccy = p[1]; ccz = p[2];
    }

    issue(0, 0);
    int buf = 0;
    const int NT = (NK / 2) / AKT;

    for (int t = 0; t < NT; t++) {
        const bool more = (t + 1) < NT;
        if (more) {
            issue(t + 1, buf ^ 1);
            asm volatile("cp.async.wait_group 1;" ::: "memory");
        } else {
            asm volatile("cp.async.wait_group 0;" ::: "memory");
        }
        // ext cols (d^2 GEMM operands) for current tile, tf32-rounded
        if (tid < AKT) {
            float* ext = sm + OFF_K + buf * KBUF + tid * KV_STR + 64;
            ext[0] = __uint_as_float(f2tf(-2.f * ccx * inv_step2));
            ext[1] = __uint_as_float(f2tf(-2.f * ccy * inv_step2));
            ext[2] = __uint_as_float(f2tf(-2.f * ccz * inv_step2));
            ext[3] = __uint_as_float(f2tf(
                fmaf(ccx, ccx, fmaf(ccy, ccy, ccz * ccz)) * inv_step2));
        }
        __syncthreads();
        if (more && tid < AKT) {
            const float* p = kcb + (size_t)(kstart + (t + 1) * AKT + tid) * 3;
            ccx = __ldg(p); ccy = __ldg(p + 1); ccz = __ldg(p + 2);
        }

        const float* Kb = sm + OFF_K + buf * KBUF;
        const float* Vb = sm + OFF_V + buf * VBUF;

        // ---- QK^T (raw tf32 frags) ----
        float sacc[4][4] = {};
        #pragma unroll
        for (int kss = 0; kss < 8; kss++) {
            const int dcol = kss * 8 + lr;
            #pragma unroll
            for (int nf = 0; nf < 4; nf++) {
                const int key = nf * 8 + lq;
                mma8(sacc[nf], qa[kss],
                     ldr(&Kb[key * KV_STR + dcol]),
                     ldr(&Kb[key * KV_STR + dcol + 4]));
            }
        }
        // ---- d^2 * inv_step2 via ext mma ----
        float dd[4][4] = {};
        #pragma unroll
        for (int nf = 0; nf < 4; nf++)
            mma8(dd[nf], qa2, ldr(&Kb[(nf * 8 + lq) * KV_STR + 64 + lr]), 0u);

        // ---- bias + no-max softmax ----
        float ps0 = 0.f, ps1 = 0.f;
        const int prow0 = (w * 16 + lq) * P_STR;
        const int prow1 = prow0 + 8 * P_STR;
        #pragma unroll
        for (int nf = 0; nf < 4; nf++) {
            float p4[4];
            const float qn2[4] = {qn2s0, qn2s0, qn2s1, qn2s1};
            #pragma unroll
            for (int j = 0; j < 4; j++) {
                float u = dd[nf][j] + qn2[j];
                int ii = (int)u; ii = min(max(ii, 0), LUT_T - 2);
                float fr = u - (float)ii;
                float lg = sacc[nf][j] + fmaf(fr, slut[ii+1] - slut[ii], slut[ii]);
                p4[j] = ex2(lg);
            }
            ps0 += p4[0] + p4[1];
            ps1 += p4[2] + p4[3];
            const int c0 = nf * 8 + 2 * lr;
            Pu[prow0 + c0]     = f2tf(p4[0]);
            Pu[prow0 + c0 + 1] = f2tf(p4[1]);
            Pu[prow1 + c0]     = f2tf(p4[2]);
            Pu[prow1 + c0 + 1] = f2tf(p4[3]);
        }
        l0 += ps0;
        l1 += ps1;
        __syncwarp();

        // ---- P V ----
        #pragma unroll
        for (int kst = 0; kst < 4; kst++) {
            uint32_t pa[4];
            const int pc = kst * 8 + lr;
            pa[0] = Pu[(w * 16 + lq) * P_STR + pc];
            pa[1] = Pu[(w * 16 + lq + 8) * P_STR + pc];
            pa[2] = Pu[(w * 16 + lq) * P_STR + pc + 4];
            pa[3] = Pu[(w * 16 + lq + 8) * P_STR + pc + 4];
            #pragma unroll
            for (int nf = 0; nf < 8; nf++) {
                const int dcol = nf * 8 + lq;
                mma8(of[nf], pa,
                     ldr(&Vb[(kst * 8 + lr) * V_STR + dcol]),
                     ldr(&Vb[(kst * 8 + lr + 4) * V_STR + dcol]));
            }
        }

        __syncthreads();
        buf ^= 1;
    }

    // epilogue: unnormalized partial + l
    float* pO = ks ? g_O2 : g_attn;
    const size_t r0 = ((size_t)(b * NQ + q0 + w * 16 + lq)) * HID_ + h * HD_;
    const size_t r1 = r0 + 8 * HID_;
    #pragma unroll
    for (int nf = 0; nf < 8; nf++) {
        const int c = nf * 8 + 2 * lr;
        *(float2*)&pO[r0 + c] = make_float2(of[nf][0], of[nf][1]);
        *(float2*)&pO[r1 + c] = make_float2(of[nf][2], of[nf][3]);
    }
    // l reduce across lr lanes already done? ps summed per thread over its 4 cols;
    // need sum over lr quads (cols split across lr) -> shfl
    l0 += __shfl_xor_sync(0xffffffffu, l0, 1);
    l0 += __shfl_xor_sync(0xffffffffu, l0, 2);
    l1 += __shfl_xor_sync(0xffffffffu, l1, 1);
    l1 += __shfl_xor_sync(0xffffffffu, l1, 2);
    if (lr == 0) {
        const size_t base = (((size_t)ks * B_ + b) * H_ + h) * NQ;
        const int qr = q0 + w * 16 + lq;
        g_l[base + qr]     = l0;
        g_l[base + qr + 8] = l1;
    }
}

// ---------------------------------------------------------------------------
// Split-K merge: O = (O_A + O_B) / (l_A + l_B); store tf32-pattern for out-proj
// ---------------------------------------------------------------------------
__global__ __launch_bounds__(512) void merge_kernel()
{
    const int row = blockIdx.x;              // b*NQ + q
    const int b = row >> 10;
    const int q = row & 1023;
    const int c = threadIdx.x;
    const int h = c >> 6;

    const float lA = g_l[(((size_t)0 * B_ + b) * H_ + h) * NQ + q];
    const float lB = g_l[(((size_t)1 * B_ + b) * H_ + h) * NQ + q];
    const float inv = __fdividef(1.f, lA + lB);

    const size_t o = (size_t)row * HID_ + c;
    g_attn[o] = __uint_as_float(f2tf((g_attn[o] + g_O2[o]) * inv));
}

// ---------------------------------------------------------------------------
extern "C" void kernel_launch(void* const* d_in, const int* in_sizes, int n_in,
                              void* d_out, int out_size)
{
    const float* q_in      = (const float*)d_in[0];
    const float* kv_in     = (const float*)d_in[1];
    const float* q_coords  = (const float*)d_in[2];
    const float* kv_coords = (const float*)d_in[3];
    const float* Wq        = (const float*)d_in[4];
    const float* Wk        = (const float*)d_in[5];
    const float* Wv        = (const float*)d_in[6];
    const float* Wo        = (const float*)d_in[7];
    const float* W1        = (const float*)d_in[8];
    const float* b1        = (const float*)d_in[9];
    const float* W2        = (const float*)d_in[10];
    const float* b2        = (const float*)d_in[11];
    float* out             = (float*)d_out;

    static bool attr_set = false;
    if (!attr_set) {
        cudaFuncSetAttribute(attn_kernel,
            cudaFuncAttributeMaxDynamicSharedMemorySize, ATT_SMEM_FLOATS * 4);
        cudaFuncSetAttribute(gemm_qkv_kernel,
            cudaFuncAttributeMaxDynamicSharedMemorySize, 3 * (2560 + 2176) * 4);
        cudaFuncSetAttribute(gemm_out_kernel,
            cudaFuncAttributeMaxDynamicSharedMemorySize, 3 * (2560 + 1152) * 4);
        attr_set = true;
    }

    // bias LUT pipeline + tf32 input conversion
    init_kernel<<<1, 32>>>();
    norm_kernel<<<(B_ * NQ + B_ * NK + 255) / 256, 256>>>(q_coords, kv_coords);
    lut_kernel<<<(LUT_T + 255) / 256, 256>>>(W1, b1, W2, b2);
    conv_kernel<<<4096, 256>>>((const float4*)q_in, (const float4*)kv_in,
                               (const float4*)Wq, (const float4*)Wk,
                               (const float4*)Wv, (const float4*)Wo);

    // Fused Q/K/V projections (raw tf32, 3-stage cp.async)
    gemm_qkv_kernel<<<dim3(HID_ / 128, 80), 256, 3 * (2560 + 2176) * 4>>>();

    // Flash attention: split-K(2), no-max softmax, ext-mma bias
    attn_kernel<<<dim3(NQ / 64, H_, B_ * 2), 128, ATT_SMEM_FLOATS * 4>>>(
        q_coords, kv_coords);

    // Merge partials (writes tf32-pattern for out-proj)
    merge_kernel<<<B_ * NQ, 512>>>();

    // Output projection
    gemm_out_kernel<<<dim3(DIM_ / 64, (B_ * NQ) / 128), 256,
                      3 * (2560 + 1152) * 4>>>(out);
}

// round 8
// speedup vs baseline: 1.3050x; 1.0381x over previous
#include <cuda_runtime.h>
#include <math.h>
#include <stdint.h>

#define B_    2
#define NQ    1024
#define NK    2048
#define DIM_  512
#define HID_  512
#define H_    8
#define HD_   64
#define RBH   64
#define LUT_T 2048
#define LOG2E 1.4426950408889634f

// Static device scratch
__device__ float g_Q[(size_t)B_ * NQ * HID_];      // tf32-pattern, pre-scaled by 0.125*log2e
__device__ float g_K[(size_t)B_ * NK * HID_];      // tf32-pattern
__device__ float g_V[(size_t)B_ * NK * HID_];      // tf32-pattern
__device__ float g_attn[(size_t)B_ * NQ * HID_];   // split-0 partial -> merged (tf32-pattern)
__device__ float g_O2[(size_t)B_ * NQ * HID_];     // split-1 partial
__device__ float g_l[2 * B_ * H_ * NQ];            // softmax denoms
__device__ float g_lut[H_ * LUT_T];                // bias(d^2) * log2e
__device__ unsigned int g_maxbits[2] = {0u, 0u};   // idempotent across graph replays
__device__ float g_inv_step2;

// tf32-pattern copies of harness inputs
__device__ float g_QinT[(size_t)B_ * NQ * DIM_];
__device__ float g_KvT[(size_t)B_ * NK * DIM_];
__device__ float g_WqT[DIM_ * HID_];
__device__ float g_WkT[DIM_ * HID_];
__device__ float g_WvT[DIM_ * HID_];
__device__ float g_WoT[HID_ * DIM_];

// ---------------------------------------------------------------------------
__device__ __forceinline__ uint32_t f2tf(float x) {
    uint32_t r; asm("cvt.rna.tf32.f32 %0, %1;" : "=r"(r) : "f"(x)); return r;
}
__device__ __forceinline__ float ex2(float x) {
    float y; asm("ex2.approx.f32 %0, %1;" : "=f"(y) : "f"(x)); return y;
}
__device__ __forceinline__ void mma8(float* d, const uint32_t* a, uint32_t b0, uint32_t b1) {
    asm volatile(
        "mma.sync.aligned.m16n8k8.row.col.f32.tf32.tf32.f32 "
        "{%0,%1,%2,%3}, {%4,%5,%6,%7}, {%8,%9}, {%0,%1,%2,%3};"
        : "+f"(d[0]), "+f"(d[1]), "+f"(d[2]), "+f"(d[3])
        : "r"(a[0]), "r"(a[1]), "r"(a[2]), "r"(a[3]), "r"(b0), "r"(b1));
}
__device__ __forceinline__ void cpa16(uint32_t s, const float* g) {
    asm volatile("cp.async.cg.shared.global [%0], [%1], 16;" :: "r"(s), "l"(g));
}
__device__ __forceinline__ uint32_t s2u(const void* p) {
    return (uint32_t)__cvta_generic_to_shared(p);
}
__device__ __forceinline__ uint32_t ldr(const float* p) {
    return __float_as_uint(*p);
}

// ---------------------------------------------------------------------------
// conv + norm fused: tf32-round all matmul inputs; coord-norm atomicMax
// ---------------------------------------------------------------------------
__global__ __launch_bounds__(256) void conv_kernel(
    const float4* __restrict__ qin, const float4* __restrict__ kvin,
    const float4* __restrict__ wq, const float4* __restrict__ wk,
    const float4* __restrict__ wv, const float4* __restrict__ wo,
    const float* __restrict__ qc, const float* __restrict__ kc)
{
    int i = blockIdx.x * 256 + threadIdx.x;
    float4 v; float4* dst;
    if      (i < 262144) { v = qin[i];            dst = (float4*)g_QinT + i; }
    else if (i < 786432) { v = kvin[i - 262144];  dst = (float4*)g_KvT + (i - 262144); }
    else if (i < 851968) { v = wq[i - 786432];    dst = (float4*)g_WqT + (i - 786432); }
    else if (i < 917504) { v = wk[i - 851968];    dst = (float4*)g_WkT + (i - 851968); }
    else if (i < 983040) { v = wv[i - 917504];    dst = (float4*)g_WvT + (i - 917504); }
    else                 { v = wo[i - 983040];    dst = (float4*)g_WoT + (i - 983040); }
    v.x = __uint_as_float(f2tf(v.x));
    v.y = __uint_as_float(f2tf(v.y));
    v.z = __uint_as_float(f2tf(v.z));
    v.w = __uint_as_float(f2tf(v.w));
    *dst = v;

    // fused coord-norm max (first 6144 threads)
    const int NQT = B_ * NQ, NKT = B_ * NK;
    if (i < NQT + NKT) {
        float n; int which;
        if (i < NQT) {
            float x = qc[i*3], y = qc[i*3+1], z = qc[i*3+2];
            n = sqrtf(fmaf(x,x,fmaf(y,y,z*z))); which = 0;
        } else {
            int j = i - NQT;
            float x = kc[j*3], y = kc[j*3+1], z = kc[j*3+2];
            n = sqrtf(fmaf(x,x,fmaf(y,y,z*z))); which = 1;
        }
        atomicMax(&g_maxbits[which], __float_as_uint(n));
    }
}

__global__ __launch_bounds__(256) void lut_kernel(
    const float* __restrict__ W1, const float* __restrict__ b1,
    const float* __restrict__ W2, const float* __restrict__ b2)
{
    __shared__ float sW1[RBH], sb1[RBH], sW2[RBH * H_];
    int t = threadIdx.x;
    if (t < RBH) { sW1[t] = W1[t]; sb1[t] = b1[t]; }
    for (int i = t; i < RBH * H_; i += 256) sW2[i] = W2[i];
    __syncthreads();

    float dmax = __uint_as_float(g_maxbits[0]) + __uint_as_float(g_maxbits[1]) + 1e-3f;
    float step2 = dmax * dmax / (float)(LUT_T - 1);
    if (blockIdx.x == 0 && t == 0) g_inv_step2 = 1.0f / step2;

    int i = blockIdx.x * 256 + t;
    if (i >= LUT_T) return;
    float d = sqrtf(step2 * (float)i);

    float o[H_];
    #pragma unroll
    for (int hh = 0; hh < H_; hh++) o[hh] = b2[hh];
    #pragma unroll 8
    for (int j = 0; j < RBH; j++) {
        float x = fmaf(d, sW1[j], sb1[j]);
        float s = __fdividef(x, 1.0f + __expf(-x));
        #pragma unroll
        for (int hh = 0; hh < H_; hh++)
            o[hh] = fmaf(s, sW2[j * H_ + hh], o[hh]);
    }
    #pragma unroll
    for (int hh = 0; hh < H_; hh++)
        g_lut[hh * LUT_T + i] = o[hh] * LOG2E;
}

// ---------------------------------------------------------------------------
// Raw-tf32 GEMM body, templated tile: BMxBN, BK=16, 3-stage cp.async, 256 thr.
// mode: 0 plain store, 1 f2tf, 2 f2tf(x*QSC)
// ---------------------------------------------------------------------------
#define QSC (0.125f * LOG2E)

template<int BM, int BN>
__device__ __forceinline__ void gemm_raw_body(
    const float* __restrict__ A, const float* __restrict__ Bm,
    float* __restrict__ C, int N, int K, int row0, int mode, float* sm)
{
    constexpr int BSr = BN + 8;
    constexpr int ASZ = BM * 20, BSZ = 16 * BSr;
    constexpr int MF  = BM / 64;
    constexpr int NF  = BN / 16;
    float* As = sm;
    float* Bs = sm + 3 * ASZ;

    const int tid = threadIdx.x;
    const int lane = tid & 31, wid = tid >> 5;
    const int wm = (wid >> 1) * (BM / 4), wn = (wid & 1) * (BN / 2);
    const int col0 = blockIdx.x * BN;
    const int lq = lane >> 2, lr = lane & 3;

    const int ar = (BM == 128) ? (tid >> 1) : (tid >> 2);
    const int ac = (BM == 128) ? ((tid & 1) * 8) : ((tid & 3) * 4);
    const int bk = tid >> 4, bn = (tid & 15) * (BN / 16);

    float acc[MF][NF][4] = {};

    auto issue = [&](int k0) {
        const int st = (k0 >> 4) % 3;
        uint32_t a_s = s2u(&As[st * ASZ + ar * 20 + ac]);
        const float* ag = A + (size_t)(row0 + ar) * K + k0 + ac;
        cpa16(a_s, ag);
        if (BM == 128) cpa16(a_s + 16, ag + 4);
        uint32_t b_s = s2u(&Bs[st * BSZ + bk * BSr + bn]);
        const float* bg = Bm + (size_t)(k0 + bk) * N + col0 + bn;
        cpa16(b_s, bg);
        if (BN == 128) cpa16(b_s + 16, bg + 4);
        asm volatile("cp.async.commit_group;" ::: "memory");
    };

    issue(0); issue(16);

    for (int k0 = 0; k0 < K; k0 += 16) {
        if (k0 + 32 < K) {
            asm volatile("cp.async.wait_group 1;" ::: "memory");
            __syncthreads();
            issue(k0 + 32);
        } else if (k0 + 16 < K) {
            asm volatile("cp.async.wait_group 1;" ::: "memory");
            __syncthreads();
        } else {
            asm volatile("cp.async.wait_group 0;" ::: "memory");
            __syncthreads();
        }
        const int st = (k0 >> 4) % 3;
        const float* Ab = As + st * ASZ;
        const float* Bb = Bs + st * BSZ;

        #pragma unroll
        for (int s = 0; s < 2; s++) {
            const int kc_ = s * 8 + lr;
            uint32_t af[MF][4], bfr[NF][2];
            #pragma unroll
            for (int mf = 0; mf < MF; mf++) {
                const int r = wm + mf * 16 + lq;
                af[mf][0] = ldr(&Ab[r * 20 + kc_]);
                af[mf][1] = ldr(&Ab[(r + 8) * 20 + kc_]);
                af[mf][2] = ldr(&Ab[r * 20 + kc_ + 4]);
                af[mf][3] = ldr(&Ab[(r + 8) * 20 + kc_ + 4]);
            }
            #pragma unroll
            for (int nf = 0; nf < NF; nf++) {
                const int cc = wn + nf * 8 + lq;
                bfr[nf][0] = ldr(&Bb[kc_ * BSr + cc]);
                bfr[nf][1] = ldr(&Bb[(kc_ + 4) * BSr + cc]);
            }
            #pragma unroll
            for (int mf = 0; mf < MF; mf++)
                #pragma unroll
                for (int nf = 0; nf < NF; nf++)
                    mma8(acc[mf][nf], af[mf], bfr[nf][0], bfr[nf][1]);
        }
    }

    #pragma unroll
    for (int mf = 0; mf < MF; mf++)
        #pragma unroll
        for (int nf = 0; nf < NF; nf++) {
            const int r = row0 + wm + mf * 16 + lq;
            const int c = col0 + wn + nf * 8 + 2 * lr;
            float v[4] = {acc[mf][nf][0], acc[mf][nf][1], acc[mf][nf][2], acc[mf][nf][3]};
            if (mode == 1) {
                #pragma unroll
                for (int u = 0; u < 4; u++) v[u] = __uint_as_float(f2tf(v[u]));
            } else if (mode == 2) {
                #pragma unroll
                for (int u = 0; u < 4; u++) v[u] = __uint_as_float(f2tf(v[u] * QSC));
            }
            *(float2*)&C[(size_t)r * N + c]       = make_float2(v[0], v[1]);
            *(float2*)&C[(size_t)(r + 8) * N + c] = make_float2(v[2], v[3]);
        }
}

#define QKV_SMEM (3 * (128 * 20 + 16 * 136) * 4)
#define OUT_SMEM (3 * (64 * 20 + 16 * 72) * 4)

// QKV fused: blockIdx.y [0,16)->Q(mode2), [16,48)->K(mode1), [48,80)->V(mode1)
__global__ __launch_bounds__(256, 2) void gemm_qkv_kernel()
{
    extern __shared__ float gsm[];
    int by = blockIdx.y;
    const float *A, *Bw; float* C; int mode;
    if (by < 16)      { A = g_QinT; Bw = g_WqT; C = g_Q; mode = 2; }
    else if (by < 48) { A = g_KvT;  Bw = g_WkT; C = g_K; mode = 1; by -= 16; }
    else              { A = g_KvT;  Bw = g_WvT; C = g_V; mode = 1; by -= 48; }
    gemm_raw_body<128, 128>(A, Bw, C, HID_, DIM_, by * 128, mode, gsm);
}

// Out projection: 64x64 tiles for 256-CTA fill
__global__ __launch_bounds__(256, 3) void gemm_out_kernel(float* __restrict__ out)
{
    extern __shared__ float gsm[];
    gemm_raw_body<64, 64>(g_attn, g_WoT, out, DIM_, HID_, blockIdx.y * 64, 0, gsm);
}

// ---------------------------------------------------------------------------
// TF32 flash attention, CTA split-K(2), no-max softmax.
// CTA = 64 q x 1024 keys, 128 thr / 4 warps, 32-key tiles, 4 CTAs/SM.
// ---------------------------------------------------------------------------
#define AKT    32
#define KV_STR 76
#define V_STR  72
#define P_STR  36
#define KBUF   (AKT * KV_STR)
#define VBUF   (AKT * V_STR)
#define OFF_K   0
#define OFF_V   4864
#define OFF_P   9472
#define OFF_LUT 11776
#define ATT_SMEM_FLOATS 13824            // 55296 B

__global__ __launch_bounds__(128, 4) void attn_kernel(
    const float* __restrict__ qc, const float* __restrict__ kc)
{
    extern __shared__ float sm[];
    float*    slut = sm + OFF_LUT;
    uint32_t* Pu   = (uint32_t*)(sm + OFF_P);

    const int b   = blockIdx.z >> 1;
    const int ks  = blockIdx.z & 1;
    const int h   = blockIdx.y;
    const int q0  = blockIdx.x * 64;
    const int tid = threadIdx.x;
    const int lane = tid & 31;
    const int w    = tid >> 5;
    const int lq   = lane >> 2;
    const int lr   = lane & 3;
    const int kstart = ks * (NK / 2);

    for (int i = tid; i < LUT_T; i += 128) slut[i] = g_lut[h * LUT_T + i];
    const float inv_step2 = g_inv_step2;

    uint32_t qa[8][4], qa2[4];
    float qn2s0, qn2s1;
    {
        const size_t r0 = ((size_t)(b * NQ + q0 + w * 16 + lq)) * HID_ + h * HD_;
        const size_t r1 = r0 + 8 * HID_;
        #pragma unroll
        for (int kss = 0; kss < 8; kss++) {
            qa[kss][0] = ldr(&g_Q[r0 + kss * 8 + lr]);
            qa[kss][1] = ldr(&g_Q[r1 + kss * 8 + lr]);
            qa[kss][2] = ldr(&g_Q[r0 + kss * 8 + lr + 4]);
            qa[kss][3] = ldr(&g_Q[r1 + kss * 8 + lr + 4]);
        }
        const float* p0 = qc + ((size_t)b * NQ + q0 + w * 16 + lq) * 3;
        const float* p1 = p0 + 8 * 3;
        float c0[4] = {p0[0], p0[1], p0[2], 1.0f};
        float c1[4] = {p1[0], p1[1], p1[2], 1.0f};
        qa2[0] = f2tf(c0[lr]);
        qa2[1] = f2tf(c1[lr]);
        qa2[2] = 0u; qa2[3] = 0u;
        qn2s0 = fmaf(c0[0], c0[0], fmaf(c0[1], c0[1], c0[2] * c0[2])) * inv_step2;
        qn2s1 = fmaf(c1[0], c1[0], fmaf(c1[1], c1[1], c1[2] * c1[2])) * inv_step2;
    }

    float of[8][4] = {};
    float l0 = 0.f, l1 = 0.f;

    const float* Kp  = g_K + ((size_t)b * NK) * HID_ + h * HD_;
    const float* Vp  = g_V + ((size_t)b * NK) * HID_ + h * HD_;
    const float* kcb = kc + (size_t)b * NK * 3;

    const int lkey = tid >> 2;
    const int qo   = (tid & 3) * 16;

    auto issue = [&](int t, int bf) {
        const size_t kg = (size_t)(kstart + t * AKT + lkey) * HID_ + qo;
        uint32_t kd = s2u(sm + OFF_K + bf * KBUF + lkey * KV_STR + qo);
        uint32_t vd = s2u(sm + OFF_V + bf * VBUF + lkey * V_STR + qo);
        #pragma unroll
        for (int u = 0; u < 4; u++) cpa16(kd + u * 16, Kp + kg + u * 4);
        #pragma unroll
        for (int u = 0; u < 4; u++) cpa16(vd + u * 16, Vp + kg + u * 4);
        asm volatile("cp.async.commit_group;" ::: "memory");
    };

    float ccx = 0.f, ccy = 0.f, ccz = 0.f;
    if (tid < AKT) {
        const float* p = kcb + (size_t)(kstart + tid) * 3;
        ccx = p[0]; ccy = p[1]; ccz = p[2];
    }

    issue(0, 0);
    int buf = 0;
    const int NT = (NK / 2) / AKT;

    for (int t = 0; t < NT; t++) {
        const bool more = (t + 1) < NT;
        if (more) {
            issue(t + 1, buf ^ 1);
            asm volatile("cp.async.wait_group 1;" ::: "memory");
        } else {
            asm volatile("cp.async.wait_group 0;" ::: "memory");
        }
        if (tid < AKT) {
            float* ext = sm + OFF_K + buf * KBUF + tid * KV_STR + 64;
            ext[0] = __uint_as_float(f2tf(-2.f * ccx * inv_step2));
            ext[1] = __uint_as_float(f2tf(-2.f * ccy * inv_step2));
            ext[2] = __uint_as_float(f2tf(-2.f * ccz * inv_step2));
            ext[3] = __uint_as_float(f2tf(
                fmaf(ccx, ccx, fmaf(ccy, ccy, ccz * ccz)) * inv_step2));
        }
        __syncthreads();
        if (more && tid < AKT) {
            const float* p = kcb + (size_t)(kstart + (t + 1) * AKT + tid) * 3;
            ccx = __ldg(p); ccy = __ldg(p + 1); ccz = __ldg(p + 2);
        }

        const float* Kb = sm + OFF_K + buf * KBUF;
        const float* Vb = sm + OFF_V + buf * VBUF;

        // ---- QK^T ----
        float sacc[4][4] = {};
        #pragma unroll
        for (int kss = 0; kss < 8; kss++) {
            const int dcol = kss * 8 + lr;
            #pragma unroll
            for (int nf = 0; nf < 4; nf++) {
                const int key = nf * 8 + lq;
                mma8(sacc[nf], qa[kss],
                     ldr(&Kb[key * KV_STR + dcol]),
                     ldr(&Kb[key * KV_STR + dcol + 4]));
            }
        }

        // ---- bias (d^2 mma inline) + no-max softmax ----
        float ps0 = 0.f, ps1 = 0.f;
        const int prow0 = (w * 16 + lq) * P_STR;
        const int prow1 = prow0 + 8 * P_STR;
        #pragma unroll
        for (int nf = 0; nf < 4; nf++) {
            float dd4[4] = {};
            mma8(dd4, qa2, ldr(&Kb[(nf * 8 + lq) * KV_STR + 64 + lr]), 0u);
            float p4[4];
            const float qn2[4] = {qn2s0, qn2s0, qn2s1, qn2s1};
            #pragma unroll
            for (int j = 0; j < 4; j++) {
                float u = dd4[j] + qn2[j];
                int ii = (int)u; ii = min(max(ii, 0), LUT_T - 2);
                float fr = u - (float)ii;
                float lg = sacc[nf][j] + fmaf(fr, slut[ii+1] - slut[ii], slut[ii]);
                p4[j] = ex2(lg);
            }
            ps0 += p4[0] + p4[1];
            ps1 += p4[2] + p4[3];
            const int c0 = nf * 8 + 2 * lr;
            Pu[prow0 + c0]     = f2tf(p4[0]);
            Pu[prow0 + c0 + 1] = f2tf(p4[1]);
            Pu[prow1 + c0]     = f2tf(p4[2]);
            Pu[prow1 + c0 + 1] = f2tf(p4[3]);
        }
        l0 += ps0;
        l1 += ps1;
        __syncwarp();

        // ---- P V ----
        #pragma unroll
        for (int kst = 0; kst < 4; kst++) {
            uint32_t pa[4];
            const int pc = kst * 8 + lr;
            pa[0] = Pu[(w * 16 + lq) * P_STR + pc];
            pa[1] = Pu[(w * 16 + lq + 8) * P_STR + pc];
            pa[2] = Pu[(w * 16 + lq) * P_STR + pc + 4];
            pa[3] = Pu[(w * 16 + lq + 8) * P_STR + pc + 4];
            #pragma unroll
            for (int nf = 0; nf < 8; nf++) {
                const int dcol = nf * 8 + lq;
                mma8(of[nf], pa,
                     ldr(&Vb[(kst * 8 + lr) * V_STR + dcol]),
                     ldr(&Vb[(kst * 8 + lr + 4) * V_STR + dcol]));
            }
        }

        __syncthreads();
        buf ^= 1;
    }

    // epilogue
    float* pO = ks ? g_O2 : g_attn;
    const size_t r0 = ((size_t)(b * NQ + q0 + w * 16 + lq)) * HID_ + h * HD_;
    const size_t r1 = r0 + 8 * HID_;
    #pragma unroll
    for (int nf = 0; nf < 8; nf++) {
        const int c = nf * 8 + 2 * lr;
        *(float2*)&pO[r0 + c] = make_float2(of[nf][0], of[nf][1]);
        *(float2*)&pO[r1 + c] = make_float2(of[nf][2], of[nf][3]);
    }
    l0 += __shfl_xor_sync(0xffffffffu, l0, 1);
    l0 += __shfl_xor_sync(0xffffffffu, l0, 2);
    l1 += __shfl_xor_sync(0xffffffffu, l1, 1);
    l1 += __shfl_xor_sync(0xffffffffu, l1, 2);
    if (lr == 0) {
        const size_t base = (((size_t)ks * B_ + b) * H_ + h) * NQ;
        const int qr = q0 + w * 16 + lq;
        g_l[base + qr]     = l0;
        g_l[base + qr + 8] = l1;
    }
}

// ---------------------------------------------------------------------------
__global__ __launch_bounds__(512) void merge_kernel()
{
    const int row = blockIdx.x;
    const int b = row >> 10;
    const int q = row & 1023;
    const int c = threadIdx.x;
    const int h = c >> 6;

    const float lA = g_l[(((size_t)0 * B_ + b) * H_ + h) * NQ + q];
    const float lB = g_l[(((size_t)1 * B_ + b) * H_ + h) * NQ + q];
    const float inv = __fdividef(1.f, lA + lB);

    const size_t o = (size_t)row * HID_ + c;
    g_attn[o] = __uint_as_float(f2tf((g_attn[o] + g_O2[o]) * inv));
}

// ---------------------------------------------------------------------------
extern "C" void kernel_launch(void* const* d_in, const int* in_sizes, int n_in,
                              void* d_out, int out_size)
{
    const float* q_in      = (const float*)d_in[0];
    const float* kv_in     = (const float*)d_in[1];
    const float* q_coords  = (const float*)d_in[2];
    const float* kv_coords = (const float*)d_in[3];
    const float* Wq        = (const float*)d_in[4];
    const float* Wk        = (const float*)d_in[5];
    const float* Wv        = (const float*)d_in[6];
    const float* Wo        = (const float*)d_in[7];
    const float* W1        = (const float*)d_in[8];
    const float* b1        = (const float*)d_in[9];
    const float* W2        = (const float*)d_in[10];
    const float* b2        = (const float*)d_in[11];
    float* out             = (float*)d_out;

    static bool attr_set = false;
    if (!attr_set) {
        cudaFuncSetAttribute(attn_kernel,
            cudaFuncAttributeMaxDynamicSharedMemorySize, ATT_SMEM_FLOATS * 4);
        cudaFuncSetAttribute(gemm_qkv_kernel,
            cudaFuncAttributeMaxDynamicSharedMemorySize, QKV_SMEM);
        cudaFuncSetAttribute(gemm_out_kernel,
            cudaFuncAttributeMaxDynamicSharedMemorySize, OUT_SMEM);
        attr_set = true;
    }

    // tf32 conversion + coord norms (fused), then LUT
    conv_kernel<<<4096, 256>>>((const float4*)q_in, (const float4*)kv_in,
                               (const float4*)Wq, (const float4*)Wk,
                               (const float4*)Wv, (const float4*)Wo,
                               q_coords, kv_coords);
    lut_kernel<<<(LUT_T + 255) / 256, 256>>>(W1, b1, W2, b2);

    // Fused Q/K/V projections
    gemm_qkv_kernel<<<dim3(HID_ / 128, 80), 256, QKV_SMEM>>>();

    // Flash attention: split-K(2), single wave at 4 CTAs/SM
    attn_kernel<<<dim3(NQ / 64, H_, B_ * 2), 128, ATT_SMEM_FLOATS * 4>>>(
        q_coords, kv_coords);

    // Merge partials
    merge_kernel<<<B_ * NQ, 512>>>();

    // Output projection (64x64 tiles, 256 CTAs)
    gemm_out_kernel<<<dim3(DIM_ / 64, (B_ * NQ) / 64), 256, OUT_SMEM>>>(out);
}

// round 9
// speedup vs baseline: 1.3428x; 1.0290x over previous
#include <cuda_runtime.h>
#include <math.h>
#include <stdint.h>

#define B_    2
#define NQ    1024
#define NK    2048
#define DIM_  512
#define HID_  512
#define H_    8
#define HD_   64
#define RBH   64
#define LUT_N 1024
#define LOG2E 1.4426950408889634f

// Static device scratch
__device__ float g_Q[(size_t)B_ * NQ * HID_];      // tf32-pattern, pre-scaled by 0.125*log2e
__device__ float g_K[(size_t)B_ * NK * HID_];      // tf32-pattern
__device__ float g_V[(size_t)B_ * NK * HID_];      // tf32-pattern
__device__ float g_attn[(size_t)B_ * NQ * HID_];   // split-0 partial -> merged (tf32-pattern)
__device__ float g_O2[(size_t)B_ * NQ * HID_];     // split-1 partial
__device__ float g_l[2 * B_ * H_ * NQ];            // softmax denoms
__device__ float g_lut[H_ * LUT_N];                // bias(d^2) * log2e
__device__ unsigned int g_maxbits[2] = {0u, 0u};
__device__ float g_inv_step2;

// tf32-pattern copies of harness inputs
__device__ float g_QinT[(size_t)B_ * NQ * DIM_];
__device__ float g_KvT[(size_t)B_ * NK * DIM_];
__device__ float g_WqT[DIM_ * HID_];
__device__ float g_WkT[DIM_ * HID_];
__device__ float g_WvT[DIM_ * HID_];
__device__ float g_WoT[HID_ * DIM_];

// ---------------------------------------------------------------------------
__device__ __forceinline__ uint32_t f2tf(float x) {
    uint32_t r; asm("cvt.rna.tf32.f32 %0, %1;" : "=r"(r) : "f"(x)); return r;
}
__device__ __forceinline__ float ex2(float x) {
    float y; asm("ex2.approx.f32 %0, %1;" : "=f"(y) : "f"(x)); return y;
}
__device__ __forceinline__ void mma8(float* d, const uint32_t* a, uint32_t b0, uint32_t b1) {
    asm volatile(
        "mma.sync.aligned.m16n8k8.row.col.f32.tf32.tf32.f32 "
        "{%0,%1,%2,%3}, {%4,%5,%6,%7}, {%8,%9}, {%0,%1,%2,%3};"
        : "+f"(d[0]), "+f"(d[1]), "+f"(d[2]), "+f"(d[3])
        : "r"(a[0]), "r"(a[1]), "r"(a[2]), "r"(a[3]), "r"(b0), "r"(b1));
}
__device__ __forceinline__ void ldsm4(uint32_t* r, uint32_t saddr) {
    asm volatile("ldmatrix.sync.aligned.m8n8.x4.shared.b16 {%0,%1,%2,%3}, [%4];"
        : "=r"(r[0]), "=r"(r[1]), "=r"(r[2]), "=r"(r[3]) : "r"(saddr));
}
__device__ __forceinline__ void cpa16(uint32_t s, const float* g) {
    asm volatile("cp.async.cg.shared.global [%0], [%1], 16;" :: "r"(s), "l"(g));
}
__device__ __forceinline__ uint32_t s2u(const void* p) {
    return (uint32_t)__cvta_generic_to_shared(p);
}
__device__ __forceinline__ uint32_t ldr(const float* p) {
    return __float_as_uint(*p);
}

// ---------------------------------------------------------------------------
// conv + norm fused
// ---------------------------------------------------------------------------
__global__ __launch_bounds__(256) void conv_kernel(
    const float4* __restrict__ qin, const float4* __restrict__ kvin,
    const float4* __restrict__ wq, const float4* __restrict__ wk,
    const float4* __restrict__ wv, const float4* __restrict__ wo,
    const float* __restrict__ qc, const float* __restrict__ kc)
{
    int i = blockIdx.x * 256 + threadIdx.x;
    float4 v; float4* dst;
    if      (i < 262144) { v = qin[i];            dst = (float4*)g_QinT + i; }
    else if (i < 786432) { v = kvin[i - 262144];  dst = (float4*)g_KvT + (i - 262144); }
    else if (i < 851968) { v = wq[i - 786432];    dst = (float4*)g_WqT + (i - 786432); }
    else if (i < 917504) { v = wk[i - 851968];    dst = (float4*)g_WkT + (i - 851968); }
    else if (i < 983040) { v = wv[i - 917504];    dst = (float4*)g_WvT + (i - 917504); }
    else                 { v = wo[i - 983040];    dst = (float4*)g_WoT + (i - 983040); }
    v.x = __uint_as_float(f2tf(v.x));
    v.y = __uint_as_float(f2tf(v.y));
    v.z = __uint_as_float(f2tf(v.z));
    v.w = __uint_as_float(f2tf(v.w));
    *dst = v;

    const int NQT = B_ * NQ, NKT = B_ * NK;
    if (i < NQT + NKT) {
        float n; int which;
        if (i < NQT) {
            float x = qc[i*3], y = qc[i*3+1], z = qc[i*3+2];
            n = sqrtf(fmaf(x,x,fmaf(y,y,z*z))); which = 0;
        } else {
            int j = i - NQT;
            float x = kc[j*3], y = kc[j*3+1], z = kc[j*3+2];
            n = sqrtf(fmaf(x,x,fmaf(y,y,z*z))); which = 1;
        }
        atomicMax(&g_maxbits[which], __float_as_uint(n));
    }
}

__global__ __launch_bounds__(256) void lut_kernel(
    const float* __restrict__ W1, const float* __restrict__ b1,
    const float* __restrict__ W2, const float* __restrict__ b2)
{
    __shared__ float sW1[RBH], sb1[RBH], sW2[RBH * H_];
    int t = threadIdx.x;
    if (t < RBH) { sW1[t] = W1[t]; sb1[t] = b1[t]; }
    for (int i = t; i < RBH * H_; i += 256) sW2[i] = W2[i];
    __syncthreads();

    float dmax = __uint_as_float(g_maxbits[0]) + __uint_as_float(g_maxbits[1]) + 1e-3f;
    float step2 = dmax * dmax / (float)(LUT_N - 1);
    if (blockIdx.x == 0 && t == 0) g_inv_step2 = 1.0f / step2;

    int i = blockIdx.x * 256 + t;
    if (i >= LUT_N) return;
    float d = sqrtf(step2 * (float)i);

    float o[H_];
    #pragma unroll
    for (int hh = 0; hh < H_; hh++) o[hh] = b2[hh];
    #pragma unroll 8
    for (int j = 0; j < RBH; j++) {
        float x = fmaf(d, sW1[j], sb1[j]);
        float s = __fdividef(x, 1.0f + __expf(-x));
        #pragma unroll
        for (int hh = 0; hh < H_; hh++)
            o[hh] = fmaf(s, sW2[j * H_ + hh], o[hh]);
    }
    #pragma unroll
    for (int hh = 0; hh < H_; hh++)
        g_lut[hh * LUT_N + i] = o[hh] * LOG2E;
}

// ---------------------------------------------------------------------------
// Raw-tf32 GEMM body, BMxBN, BK=16, 3-stage cp.async, 256 thr, LDSM A-frags.
// mode: 0 plain store, 1 f2tf, 2 f2tf(x*QSC)
// ---------------------------------------------------------------------------
#define QSC (0.125f * LOG2E)

template<int BM, int BN>
__device__ __forceinline__ void gemm_raw_body(
    const float* __restrict__ A, const float* __restrict__ Bm,
    float* __restrict__ C, int N, int K, int row0, int mode, float* sm)
{
    constexpr int BSr = BN + 8;
    constexpr int ASZ = BM * 20, BSZ = 16 * BSr;
    constexpr int MF  = BM / 64;
    constexpr int NF  = BN / 16;
    float* As = sm;
    float* Bs = sm + 3 * ASZ;

    const int tid = threadIdx.x;
    const int lane = tid & 31, wid = tid >> 5;
    const int wm = (wid >> 1) * (BM / 4), wn = (wid & 1) * (BN / 2);
    const int col0 = blockIdx.x * BN;
    const int lq = lane >> 2, lr = lane & 3;

    // LDSM lane geometry for A fragments
    const int a_lrow = ((lane >> 3) & 1) * 8 + (lane & 7);
    const int a_lcol = (lane >> 4) * 4;

    const int ar = (BM == 128) ? (tid >> 1) : (tid >> 2);
    const int ac = (BM == 128) ? ((tid & 1) * 8) : ((tid & 3) * 4);
    const int bk = tid >> 4, bn = (tid & 15) * (BN / 16);

    float acc[MF][NF][4] = {};

    auto issue = [&](int k0) {
        const int st = (k0 >> 4) % 3;
        uint32_t a_s = s2u(&As[st * ASZ + ar * 20 + ac]);
        const float* ag = A + (size_t)(row0 + ar) * K + k0 + ac;
        cpa16(a_s, ag);
        if (BM == 128) cpa16(a_s + 16, ag + 4);
        uint32_t b_s = s2u(&Bs[st * BSZ + bk * BSr + bn]);
        const float* bg = Bm + (size_t)(k0 + bk) * N + col0 + bn;
        cpa16(b_s, bg);
        if (BN == 128) cpa16(b_s + 16, bg + 4);
        asm volatile("cp.async.commit_group;" ::: "memory");
    };

    issue(0); issue(16);

    for (int k0 = 0; k0 < K; k0 += 16) {
        if (k0 + 32 < K) {
            asm volatile("cp.async.wait_group 1;" ::: "memory");
            __syncthreads();
            issue(k0 + 32);
        } else if (k0 + 16 < K) {
            asm volatile("cp.async.wait_group 1;" ::: "memory");
            __syncthreads();
        } else {
            asm volatile("cp.async.wait_group 0;" ::: "memory");
            __syncthreads();
        }
        const int st = (k0 >> 4) % 3;
        const float* Ab = As + st * ASZ;
        const float* Bb = Bs + st * BSZ;

        #pragma unroll
        for (int s = 0; s < 2; s++) {
            const int kc_ = s * 8 + lr;
            uint32_t af[MF][4], bfr[NF][2];
            #pragma unroll
            for (int mf = 0; mf < MF; mf++)
                ldsm4(af[mf], s2u(Ab) +
                      ((wm + mf * 16 + a_lrow) * 20 + s * 8 + a_lcol) * 4);
            #pragma unroll
            for (int nf = 0; nf < NF; nf++) {
                const int cc = wn + nf * 8 + lq;
                bfr[nf][0] = ldr(&Bb[kc_ * BSr + cc]);
                bfr[nf][1] = ldr(&Bb[(kc_ + 4) * BSr + cc]);
            }
            #pragma unroll
            for (int mf = 0; mf < MF; mf++)
                #pragma unroll
                for (int nf = 0; nf < NF; nf++)
                    mma8(acc[mf][nf], af[mf], bfr[nf][0], bfr[nf][1]);
        }
    }

    #pragma unroll
    for (int mf = 0; mf < MF; mf++)
        #pragma unroll
        for (int nf = 0; nf < NF; nf++) {
            const int r = row0 + wm + mf * 16 + lq;
            const int c = col0 + wn + nf * 8 + 2 * lr;
            float v[4] = {acc[mf][nf][0], acc[mf][nf][1], acc[mf][nf][2], acc[mf][nf][3]};
            if (mode == 1) {
                #pragma unroll
                for (int u = 0; u < 4; u++) v[u] = __uint_as_float(f2tf(v[u]));
            } else if (mode == 2) {
                #pragma unroll
                for (int u = 0; u < 4; u++) v[u] = __uint_as_float(f2tf(v[u] * QSC));
            }
            *(float2*)&C[(size_t)r * N + c]       = make_float2(v[0], v[1]);
            *(float2*)&C[(size_t)(r + 8) * N + c] = make_float2(v[2], v[3]);
        }
}

#define QKV_SMEM (3 * (128 * 20 + 16 * 136) * 4)
#define OUT_SMEM (3 * (64 * 20 + 16 * 72) * 4)

__global__ __launch_bounds__(256, 2) void gemm_qkv_kernel()
{
    extern __shared__ float gsm[];
    int by = blockIdx.y;
    const float *A, *Bw; float* C; int mode;
    if (by < 16)      { A = g_QinT; Bw = g_WqT; C = g_Q; mode = 2; }
    else if (by < 48) { A = g_KvT;  Bw = g_WkT; C = g_K; mode = 1; by -= 16; }
    else              { A = g_KvT;  Bw = g_WvT; C = g_V; mode = 1; by -= 48; }
    gemm_raw_body<128, 128>(A, Bw, C, HID_, DIM_, by * 128, mode, gsm);
}

__global__ __launch_bounds__(256, 3) void gemm_out_kernel(float* __restrict__ out)
{
    extern __shared__ float gsm[];
    gemm_raw_body<64, 64>(g_attn, g_WoT, out, DIM_, HID_, blockIdx.y * 64, 0, gsm);
}

// ---------------------------------------------------------------------------
// TF32 flash attention, CTA split-K(2), no-max softmax, LDSM fragments.
// CTA = 64 q x 1024 keys, 128 thr / 4 warps, 32-key tiles, 4 CTAs/SM.
// ---------------------------------------------------------------------------
#define AKT    32
#define KV_STR 76
#define V_STR  72
#define P_STR  36
#define KBUF   (AKT * KV_STR)
#define VBUF   (AKT * V_STR)
#define OFF_K   0                        // 2*2432 = 4864
#define OFF_V   4864                     // 2*2304 = 4608
#define OFF_P   9472                     // 64*36  = 2304
#define OFF_LUT 11776                    // 1024 float2 = 2048 words
#define ATT_SMEM_FLOATS 13824            // 55296 B

__global__ __launch_bounds__(128, 4) void attn_kernel(
    const float* __restrict__ qc, const float* __restrict__ kc)
{
    extern __shared__ float sm[];
    float2*   slut2 = (float2*)(sm + OFF_LUT);
    uint32_t* Pu    = (uint32_t*)(sm + OFF_P);

    const int b   = blockIdx.z >> 1;
    const int ks  = blockIdx.z & 1;
    const int h   = blockIdx.y;
    const int q0  = blockIdx.x * 64;
    const int tid = threadIdx.x;
    const int lane = tid & 31;
    const int w    = tid >> 5;
    const int lq   = lane >> 2;
    const int lr   = lane & 3;
    const int kstart = ks * (NK / 2);

    // stage LUT as (f[i], f[i+1]) pairs
    {
        const float* lb = g_lut + h * LUT_N;
        for (int i = tid; i < LUT_N - 1; i += 128)
            slut2[i] = make_float2(lb[i], lb[i + 1]);
    }
    const float inv_step2 = g_inv_step2;

    // LDSM lane geometry
    const int k_lane_off = (lane & 7) * KV_STR + (lane >> 3) * 4;       // K frags
    const uint32_t ext_addr_off = (uint32_t)(lane * KV_STR + 64) * 4;   // ext frags
    const int p_lane_off = (w * 16 + ((lane >> 3) & 1) * 8 + (lane & 7)) * P_STR
                         + (lane >> 4) * 4;                             // P frags

    uint32_t qa[8][4], qa2[4];
    float qn2s0, qn2s1;
    {
        const size_t r0 = ((size_t)(b * NQ + q0 + w * 16 + lq)) * HID_ + h * HD_;
        const size_t r1 = r0 + 8 * HID_;
        #pragma unroll
        for (int kss = 0; kss < 8; kss++) {
            qa[kss][0] = ldr(&g_Q[r0 + kss * 8 + lr]);
            qa[kss][1] = ldr(&g_Q[r1 + kss * 8 + lr]);
            qa[kss][2] = ldr(&g_Q[r0 + kss * 8 + lr + 4]);
            qa[kss][3] = ldr(&g_Q[r1 + kss * 8 + lr + 4]);
        }
        const float* p0 = qc + ((size_t)b * NQ + q0 + w * 16 + lq) * 3;
        const float* p1 = p0 + 8 * 3;
        float c0[4] = {p0[0], p0[1], p0[2], 1.0f};
        float c1[4] = {p1[0], p1[1], p1[2], 1.0f};
        qa2[0] = f2tf(c0[lr]);
        qa2[1] = f2tf(c1[lr]);
        qa2[2] = 0u; qa2[3] = 0u;
        qn2s0 = fmaf(c0[0], c0[0], fmaf(c0[1], c0[1], c0[2] * c0[2])) * inv_step2;
        qn2s1 = fmaf(c1[0], c1[0], fmaf(c1[1], c1[1], c1[2] * c1[2])) * inv_step2;
    }

    float of[8][4] = {};
    float l0 = 0.f, l1 = 0.f;

    const float* Kp  = g_K + ((size_t)b * NK) * HID_ + h * HD_;
    const float* Vp  = g_V + ((size_t)b * NK) * HID_ + h * HD_;
    const float* kcb = kc + (size_t)b * NK * 3;

    const int lkey = tid >> 2;
    const int qo   = (tid & 3) * 16;

    auto issue = [&](int t, int bf) {
        const size_t kg = (size_t)(kstart + t * AKT + lkey) * HID_ + qo;
        uint32_t kd = s2u(sm + OFF_K + bf * KBUF + lkey * KV_STR + qo);
        uint32_t vd = s2u(sm + OFF_V + bf * VBUF + lkey * V_STR + qo);
        #pragma unroll
        for (int u = 0; u < 4; u++) cpa16(kd + u * 16, Kp + kg + u * 4);
        #pragma unroll
        for (int u = 0; u < 4; u++) cpa16(vd + u * 16, Vp + kg + u * 4);
        asm volatile("cp.async.commit_group;" ::: "memory");
    };

    float ccx = 0.f, ccy = 0.f, ccz = 0.f;
    if (tid < AKT) {
        const float* p = kcb + (size_t)(kstart + tid) * 3;
        ccx = p[0]; ccy = p[1]; ccz = p[2];
    }

    issue(0, 0);
    int buf = 0;
    const int NT = (NK / 2) / AKT;
    const uint32_t zero = 0u;

    for (int t = 0; t < NT; t++) {
        const bool more = (t + 1) < NT;
        if (more) {
            issue(t + 1, buf ^ 1);
            asm volatile("cp.async.wait_group 1;" ::: "memory");
        } else {
            asm volatile("cp.async.wait_group 0;" ::: "memory");
        }
        if (tid < AKT) {
            float* ext = sm + OFF_K + buf * KBUF + tid * KV_STR + 64;
            ext[0] = __uint_as_float(f2tf(-2.f * ccx * inv_step2));
            ext[1] = __uint_as_float(f2tf(-2.f * ccy * inv_step2));
            ext[2] = __uint_as_float(f2tf(-2.f * ccz * inv_step2));
            ext[3] = __uint_as_float(f2tf(
                fmaf(ccx, ccx, fmaf(ccy, ccy, ccz * ccz)) * inv_step2));
        }
        __syncthreads();
        if (more && tid < AKT) {
            const float* p = kcb + (size_t)(kstart + (t + 1) * AKT + tid) * 3;
            ccx = __ldg(p); ccy = __ldg(p + 1); ccz = __ldg(p + 2);
        }

        const float* Kb = sm + OFF_K + buf * KBUF;
        const float* Vb = sm + OFF_V + buf * VBUF;
        const uint32_t kb_s = s2u(Kb);

        // ---- QK^T via LDSM ----
        float sacc[4][4] = {};
        #pragma unroll
        for (int nf = 0; nf < 4; nf++) {
            const uint32_t kbase = kb_s + (uint32_t)(nf * 8 * KV_STR + k_lane_off) * 4;
            #pragma unroll
            for (int j = 0; j < 4; j++) {
                uint32_t kb[4];
                ldsm4(kb, kbase + j * 64);
                mma8(sacc[nf], qa[2*j],     kb[0], kb[1]);
                mma8(sacc[nf], qa[2*j + 1], kb[2], kb[3]);
            }
        }

        // ---- d^2 ext fragments (one LDSM.x4 covers all 4 nf) ----
        uint32_t eb[4];
        ldsm4(eb, kb_s + ext_addr_off);

        // ---- bias + no-max softmax ----
        float ps0 = 0.f, ps1 = 0.f;
        const int prow0 = (w * 16 + lq) * P_STR;
        const int prow1 = prow0 + 8 * P_STR;
        #pragma unroll
        for (int nf = 0; nf < 4; nf++) {
            float dd4[4] = {qn2s0, qn2s0, qn2s1, qn2s1};   // |q|^2 folded into accum
            mma8(dd4, qa2, eb[nf], zero);
            float p4[4];
            #pragma unroll
            for (int j = 0; j < 4; j++) {
                float u = dd4[j];
                int ii = (int)u; ii = min(max(ii, 0), LUT_N - 2);
                float fr = u - (float)ii;
                float2 lh = slut2[ii];
                float lg = sacc[nf][j] + fmaf(fr, lh.y - lh.x, lh.x);
                p4[j] = ex2(lg);
            }
            ps0 += p4[0] + p4[1];
            ps1 += p4[2] + p4[3];
            const int c0 = nf * 8 + 2 * lr;
            *(uint2*)&Pu[prow0 + c0] = make_uint2(f2tf(p4[0]), f2tf(p4[1]));
            *(uint2*)&Pu[prow1 + c0] = make_uint2(f2tf(p4[2]), f2tf(p4[3]));
        }
        l0 += ps0;
        l1 += ps1;
        __syncwarp();

        // ---- P V (P via LDSM, V scalar) ----
        const uint32_t pu_s = s2u(Pu);
        #pragma unroll
        for (int kst = 0; kst < 4; kst++) {
            uint32_t pa[4];
            ldsm4(pa, pu_s + (uint32_t)(p_lane_off + kst * 8) * 4);
            #pragma unroll
            for (int nf = 0; nf < 8; nf++) {
                const int dcol = nf * 8 + lq;
                mma8(of[nf], pa,
                     ldr(&Vb[(kst * 8 + lr) * V_STR + dcol]),
                     ldr(&Vb[(kst * 8 + lr + 4) * V_STR + dcol]));
            }
        }

        __syncthreads();
        buf ^= 1;
    }

    // epilogue
    float* pO = ks ? g_O2 : g_attn;
    const size_t r0 = ((size_t)(b * NQ + q0 + w * 16 + lq)) * HID_ + h * HD_;
    const size_t r1 = r0 + 8 * HID_;
    #pragma unroll
    for (int nf = 0; nf < 8; nf++) {
        const int c = nf * 8 + 2 * lr;
        *(float2*)&pO[r0 + c] = make_float2(of[nf][0], of[nf][1]);
        *(float2*)&pO[r1 + c] = make_float2(of[nf][2], of[nf][3]);
    }
    l0 += __shfl_xor_sync(0xffffffffu, l0, 1);
    l0 += __shfl_xor_sync(0xffffffffu, l0, 2);
    l1 += __shfl_xor_sync(0xffffffffu, l1, 1);
    l1 += __shfl_xor_sync(0xffffffffu, l1, 2);
    if (lr == 0) {
        const size_t base = (((size_t)ks * B_ + b) * H_ + h) * NQ;
        const int qr = q0 + w * 16 + lq;
        g_l[base + qr]     = l0;
        g_l[base + qr + 8] = l1;
    }
}

// ---------------------------------------------------------------------------
__global__ __launch_bounds__(512) void merge_kernel()
{
    const int row = blockIdx.x;
    const int b = row >> 10;
    const int q = row & 1023;
    const int c = threadIdx.x;
    const int h = c >> 6;

    const float lA = g_l[(((size_t)0 * B_ + b) * H_ + h) * NQ + q];
    const float lB = g_l[(((size_t)1 * B_ + b) * H_ + h) * NQ + q];
    const float inv = __fdividef(1.f, lA + lB);

    const size_t o = (size_t)row * HID_ + c;
    g_attn[o] = __uint_as_float(f2tf((g_attn[o] + g_O2[o]) * inv));
}

// ---------------------------------------------------------------------------
extern "C" void kernel_launch(void* const* d_in, const int* in_sizes, int n_in,
                              void* d_out, int out_size)
{
    const float* q_in      = (const float*)d_in[0];
    const float* kv_in     = (const float*)d_in[1];
    const float* q_coords  = (const float*)d_in[2];
    const float* kv_coords = (const float*)d_in[3];
    const float* Wq        = (const float*)d_in[4];
    const float* Wk        = (const float*)d_in[5];
    const float* Wv        = (const float*)d_in[6];
    const float* Wo        = (const float*)d_in[7];
    const float* W1        = (const float*)d_in[8];
    const float* b1        = (const float*)d_in[9];
    const float* W2        = (const float*)d_in[10];
    const float* b2        = (const float*)d_in[11];
    float* out             = (float*)d_out;

    static bool attr_set = false;
    if (!attr_set) {
        cudaFuncSetAttribute(attn_kernel,
            cudaFuncAttributeMaxDynamicSharedMemorySize, ATT_SMEM_FLOATS * 4);
        cudaFuncSetAttribute(gemm_qkv_kernel,
            cudaFuncAttributeMaxDynamicSharedMemorySize, QKV_SMEM);
        cudaFuncSetAttribute(gemm_out_kernel,
            cudaFuncAttributeMaxDynamicSharedMemorySize, OUT_SMEM);
        attr_set = true;
    }

    conv_kernel<<<4096, 256>>>((const float4*)q_in, (const float4*)kv_in,
                               (const float4*)Wq, (const float4*)Wk,
                               (const float4*)Wv, (const float4*)Wo,
                               q_coords, kv_coords);
    lut_kernel<<<(LUT_N + 255) / 256, 256>>>(W1, b1, W2, b2);

    gemm_qkv_kernel<<<dim3(HID_ / 128, 80), 256, QKV_SMEM>>>();

    attn_kernel<<<dim3(NQ / 64, H_, B_ * 2), 128, ATT_SMEM_FLOATS * 4>>>(
        q_coords, kv_coords);

    merge_kernel<<<B_ * NQ, 512>>>();

    gemm_out_kernel<<<dim3(DIM_ / 64, (B_ * NQ) / 64), 256, OUT_SMEM>>>(out);
}